// round 6
// baseline (speedup 1.0000x reference)
#include <cuda_runtime.h>
#include <math.h>
#include <stdint.h>

// Problem constants
#define B_  32
#define C_  512
#define M_  784            // 28*28
#define NSQ (C_*C_)        // 262144

// ---------------- scratch ----------------
__device__ float g_A [B_*NSQ];   // covariance matrices
__device__ float g_mean[B_*C_];
__device__ float g_itr[B_];      // 1/trace
__device__ float g_str[B_];      // sqrt(trace)
__device__ float g_cs [B_*C_];   // final column means

// ================= warp-level tf32 MMA (sm_80 ISA) =================
__device__ __forceinline__ void mma_tf32(float* c, const uint32_t* a, const uint32_t* b) {
    asm volatile("mma.sync.aligned.m16n8k8.row.col.f32.tf32.tf32.f32 "
        "{%0,%1,%2,%3}, {%4,%5,%6,%7}, {%8,%9}, {%0,%1,%2,%3};"
        : "+f"(c[0]), "+f"(c[1]), "+f"(c[2]), "+f"(c[3])
        : "r"(a[0]), "r"(a[1]), "r"(a[2]), "r"(a[3]), "r"(b[0]), "r"(b[1]));
}
#define HI_MASK 0xFFFFE000u
__device__ __forceinline__ void split_tf32(float x, uint32_t& hi, uint32_t& lo) {
    uint32_t xb = __float_as_uint(x);
    hi = xb & HI_MASK;
    float lof = x - __uint_as_float(hi);
    lo = __float_as_uint(lof) & HI_MASK;
}

// ================= covariance GEMM (symmetric, upper-tri tiles only) =================
#define KCH  32
#define GT   256
#define APAD 36
#define ATILE_F (128*APAD)
#define STAGE_F (2*ATILE_F)
#define GEMM_SMEM (2*STAGE_F*4)   // 73728 bytes

__constant__ int c_bi[10] = {0,0,0,0,1,1,1,2,2,3};
__constant__ int c_bj[10] = {0,1,2,3,1,2,3,2,3,3};

__global__ void __launch_bounds__(GT)
cov_gemm(const float* __restrict__ xg, float* __restrict__ Cg,
         const float* __restrict__ meang)
{
    extern __shared__ float sm[];
    const int tid = threadIdx.x;
    const int b = blockIdx.z;
    const float* A  = xg + (long)b * C_ * M_;
    float*       C  = Cg + (long)b * NSQ;
    const int ib = c_bi[blockIdx.x] * 128;
    const int jb = c_bj[blockIdx.x] * 128;
    const int K = M_;
    const float covInvM = 1.0f / M_;

    const int wid = tid >> 5, lane = tid & 31;
    const int wm = wid & 1, wn = wid >> 1;
    const int gid = lane >> 2, tig = lane & 3;

    float acc[4][4][4];
    #pragma unroll
    for (int mf = 0; mf < 4; mf++)
        #pragma unroll
        for (int nf = 0; nf < 4; nf++)
            #pragma unroll
            for (int e = 0; e < 4; e++) acc[mf][nf][e] = 0.f;

    const int NC = (K + KCH - 1) / KCH;
    float4 ra[4], rb[4];

    #pragma unroll
    for (int q = 0; q < 4; q++) {
        int f = tid + q * GT; int r = f >> 3; int k = (f & 7) * 4;
        ra[q] = (k < K) ? *(const float4*)(A + (long)(ib + r) * M_ + k) : make_float4(0,0,0,0);
        rb[q] = (k < K) ? *(const float4*)(A + (long)(jb + r) * M_ + k) : make_float4(0,0,0,0);
    }
    #pragma unroll
    for (int q = 0; q < 4; q++) {
        int f = tid + q * GT; int r = f >> 3; int c = (f & 7) * 4;
        *(float4*)(sm + (long)r * APAD + c)           = ra[q];
        *(float4*)(sm + ATILE_F + (long)r * APAD + c) = rb[q];
    }
    __syncthreads();

    for (int i = 0; i < NC; i++) {
        if (i + 1 < NC) {
            const int k0 = (i + 1) * KCH;
            #pragma unroll
            for (int q = 0; q < 4; q++) {
                int f = tid + q * GT; int r = f >> 3; int k = k0 + (f & 7) * 4;
                ra[q] = (k < K) ? *(const float4*)(A + (long)(ib + r) * M_ + k) : make_float4(0,0,0,0);
                rb[q] = (k < K) ? *(const float4*)(A + (long)(jb + r) * M_ + k) : make_float4(0,0,0,0);
            }
        }
        const float* As = sm + (i & 1) * STAGE_F;
        const float* Bs = As + ATILE_F;
        #pragma unroll
        for (int ks = 0; ks < 4; ks++) {
            uint32_t ah[4][4], al[4][4];
            #pragma unroll
            for (int mf = 0; mf < 4; mf++) {
                int base = (wm * 64 + mf * 16 + gid) * APAD + ks * 8 + tig;
                split_tf32(As[base],                ah[mf][0], al[mf][0]);
                split_tf32(As[base + 8 * APAD],     ah[mf][1], al[mf][1]);
                split_tf32(As[base + 4],            ah[mf][2], al[mf][2]);
                split_tf32(As[base + 8 * APAD + 4], ah[mf][3], al[mf][3]);
            }
            uint32_t bh[4][2], bl[4][2];
            #pragma unroll
            for (int nf = 0; nf < 4; nf++) {
                int base = (wn * 32 + nf * 8 + gid) * APAD + ks * 8 + tig;
                split_tf32(Bs[base],     bh[nf][0], bl[nf][0]);
                split_tf32(Bs[base + 4], bh[nf][1], bl[nf][1]);
            }
            #pragma unroll
            for (int mf = 0; mf < 4; mf++)
                #pragma unroll
                for (int nf = 0; nf < 4; nf++) {
                    mma_tf32(acc[mf][nf], ah[mf], bh[nf]);
                    mma_tf32(acc[mf][nf], ah[mf], bl[nf]);
                    mma_tf32(acc[mf][nf], al[mf], bh[nf]);
                }
        }
        if (i + 1 < NC) {
            float* Ad = sm + ((i + 1) & 1) * STAGE_F;
            #pragma unroll
            for (int q = 0; q < 4; q++) {
                int f = tid + q * GT; int r = f >> 3; int c = (f & 7) * 4;
                *(float4*)(Ad + (long)r * APAD + c)           = ra[q];
                *(float4*)(Ad + ATILE_F + (long)r * APAD + c) = rb[q];
            }
        }
        __syncthreads();
    }

    const bool offdiag = (ib != jb);
    #pragma unroll
    for (int mf = 0; mf < 4; mf++) {
        const int row0 = ib + wm * 64 + mf * 16 + gid;
        float mi0 = meang[b * C_ + row0];
        float mi1 = meang[b * C_ + row0 + 8];
        #pragma unroll
        for (int nf = 0; nf < 4; nf++) {
            const int col0 = jb + wn * 32 + nf * 8 + tig * 2;
            float mj0 = meang[b * C_ + col0], mj1 = meang[b * C_ + col0 + 1];
            float c0 = acc[mf][nf][0] * covInvM - mi0 * mj0;
            float c1 = acc[mf][nf][1] * covInvM - mi0 * mj1;
            float c2 = acc[mf][nf][2] * covInvM - mi1 * mj0;
            float c3 = acc[mf][nf][3] * covInvM - mi1 * mj1;
            *(float2*)(C + (long)row0 * C_ + col0)       = make_float2(c0, c1);
            *(float2*)(C + (long)(row0 + 8) * C_ + col0) = make_float2(c2, c3);
            if (offdiag) {
                C[(long)col0 * C_ + row0]           = c0;
                C[(long)(col0 + 1) * C_ + row0]     = c1;
                C[(long)col0 * C_ + row0 + 8]       = c2;
                C[(long)(col0 + 1) * C_ + row0 + 8] = c3;
            }
        }
    }
}

// ---------------- per-row mean of x ----------------
__global__ void mean_kernel(const float* __restrict__ x, float* __restrict__ mean)
{
    int warp = (blockIdx.x * blockDim.x + threadIdx.x) >> 5;
    int lane = threadIdx.x & 31;
    if (warp >= B_*C_) return;
    const float* row = x + (long)warp * M_;
    float s = 0.f;
    for (int k = lane; k < M_; k += 32) s += row[k];
    #pragma unroll
    for (int off = 16; off; off >>= 1) s += __shfl_down_sync(0xffffffffu, s, off);
    if (lane == 0) mean[warp] = s * (1.0f / M_);
}

// ---------------- trace ----------------
__global__ void trace_kernel(const float* __restrict__ A,
                             float* __restrict__ itr, float* __restrict__ str)
{
    __shared__ float sh[512];
    const int b = blockIdx.x;
    const int i = threadIdx.x;
    sh[i] = A[(long)b * NSQ + (long)i * C_ + i];
    __syncthreads();
    for (int off = 256; off; off >>= 1) {
        if (i < off) sh[i] += sh[i + off];
        __syncthreads();
    }
    if (i == 0) { float t = sh[0]; itr[b] = 1.0f / t; str[b] = sqrtf(t); }
}

// ================= Newton-Schulz vector chain (single CTA per batch, high MLP) =================
// Ysqrt/sqrt(tr) = T * W0..W4, W_k = 1.5I - 0.5 S_k, S_0 = T, S_{k+1} = S_k W_k^2.
// 122 sequential matvecs per batch; per-step limiter is L2 latency -> maximize MLP.
struct ChainCtx {
    const float* Ab;
    float* v;          // smem current vector [512]
    float* partial;    // smem [8*512]
    float* pool;       // smem save stack [5*512]
    float  inv;
    int    tid;
};

// v <- inv * (v^T A). 1024 threads: j4 = tid&127 (4-col group), isec = tid>>7 (64 rows).
// 8 independent loads in flight per iteration, 4 rotating accumulators.
__device__ void do_matvec(ChainCtx& c)
{
    const int j4 = c.tid & 127;
    const int isec = c.tid >> 7;
    const float* base = c.Ab + (long)isec * 64 * C_ + j4 * 4;
    const float* vs = c.v + isec * 64;

    float4 A0 = make_float4(0.f,0.f,0.f,0.f), A1 = A0, A2 = A0, A3 = A0;
    #pragma unroll
    for (int ii = 0; ii < 64; ii += 8) {
        float4 t0 = *(const float4*)(base + (long)(ii + 0) * C_);
        float4 t1 = *(const float4*)(base + (long)(ii + 1) * C_);
        float4 t2 = *(const float4*)(base + (long)(ii + 2) * C_);
        float4 t3 = *(const float4*)(base + (long)(ii + 3) * C_);
        float4 t4 = *(const float4*)(base + (long)(ii + 4) * C_);
        float4 t5 = *(const float4*)(base + (long)(ii + 5) * C_);
        float4 t6 = *(const float4*)(base + (long)(ii + 6) * C_);
        float4 t7 = *(const float4*)(base + (long)(ii + 7) * C_);
        float s0 = vs[ii + 0], s1 = vs[ii + 1], s2 = vs[ii + 2], s3 = vs[ii + 3];
        float s4 = vs[ii + 4], s5 = vs[ii + 5], s6 = vs[ii + 6], s7 = vs[ii + 7];
        A0.x = fmaf(s0, t0.x, A0.x); A0.y = fmaf(s0, t0.y, A0.y);
        A0.z = fmaf(s0, t0.z, A0.z); A0.w = fmaf(s0, t0.w, A0.w);
        A1.x = fmaf(s1, t1.x, A1.x); A1.y = fmaf(s1, t1.y, A1.y);
        A1.z = fmaf(s1, t1.z, A1.z); A1.w = fmaf(s1, t1.w, A1.w);
        A2.x = fmaf(s2, t2.x, A2.x); A2.y = fmaf(s2, t2.y, A2.y);
        A2.z = fmaf(s2, t2.z, A2.z); A2.w = fmaf(s2, t2.w, A2.w);
        A3.x = fmaf(s3, t3.x, A3.x); A3.y = fmaf(s3, t3.y, A3.y);
        A3.z = fmaf(s3, t3.z, A3.z); A3.w = fmaf(s3, t3.w, A3.w);
        A0.x = fmaf(s4, t4.x, A0.x); A0.y = fmaf(s4, t4.y, A0.y);
        A0.z = fmaf(s4, t4.z, A0.z); A0.w = fmaf(s4, t4.w, A0.w);
        A1.x = fmaf(s5, t5.x, A1.x); A1.y = fmaf(s5, t5.y, A1.y);
        A1.z = fmaf(s5, t5.z, A1.z); A1.w = fmaf(s5, t5.w, A1.w);
        A2.x = fmaf(s6, t6.x, A2.x); A2.y = fmaf(s6, t6.y, A2.y);
        A2.z = fmaf(s6, t6.z, A2.z); A2.w = fmaf(s6, t6.w, A2.w);
        A3.x = fmaf(s7, t7.x, A3.x); A3.y = fmaf(s7, t7.y, A3.y);
        A3.z = fmaf(s7, t7.z, A3.z); A3.w = fmaf(s7, t7.w, A3.w);
    }
    A0.x += A1.x + A2.x + A3.x;
    A0.y += A1.y + A2.y + A3.y;
    A0.z += A1.z + A2.z + A3.z;
    A0.w += A1.w + A2.w + A3.w;
    *(float4*)(c.partial + isec * 512 + j4 * 4) = A0;
    __syncthreads();
    if (c.tid < 512) {
        float s = 0.f;
        #pragma unroll
        for (int e = 0; e < 8; e++) s += c.partial[e * 512 + c.tid];
        c.v[c.tid] = s * c.inv;
    }
    __syncthreads();
}

__device__ void applyS(int k, ChainCtx& c, int sp);

__device__ void applyW(int k, ChainCtx& c, int sp)
{
    float* save = c.pool + sp * 512;
    if (c.tid < 512) save[c.tid] = c.v[c.tid];
    __syncthreads();
    applyS(k, c, sp + 1);
    if (c.tid < 512) c.v[c.tid] = 1.5f * save[c.tid] - 0.5f * c.v[c.tid];
    __syncthreads();
}

__device__ void applyS(int k, ChainCtx& c, int sp)
{
    if (k == 0) { do_matvec(c); return; }
    applyS(k - 1, c, sp);
    applyW(k - 1, c, sp);
    applyW(k - 1, c, sp);
}

__global__ void __launch_bounds__(1024, 1)
chain_kernel(const float* __restrict__ A, const float* __restrict__ itr,
             const float* __restrict__ str, float* __restrict__ cs)
{
    __shared__ float v[512];
    __shared__ float partial[8 * 512];
    __shared__ float pool[5 * 512];
    const int b = blockIdx.x;
    const int tid = threadIdx.x;

    ChainCtx c;
    c.Ab = A + (long)b * NSQ;
    c.v = v; c.partial = partial; c.pool = pool;
    c.inv = itr[b]; c.tid = tid;

    if (tid < 512) v[tid] = 1.0f;
    __syncthreads();

    do_matvec(c);                 // u = 1^T * T
    for (int k = 0; k < 5; k++)   // u = u * W_k
        applyW(k, c, 0);

    if (tid < 512) cs[b * C_ + tid] = v[tid] * str[b] * (1.0f / C_);
}

// ---------------- out = cov_sum * x ----------------
__global__ void scale_kernel(const float* __restrict__ x,
                             const float* __restrict__ cs, float* __restrict__ out)
{
    long i4 = (long)blockIdx.x * blockDim.x + threadIdx.x;
    const long total4 = (long)B_ * C_ * M_ / 4;
    if (i4 >= total4) return;
    long e = i4 * 4;
    int bc = (int)(e / M_);
    float s = cs[bc];
    float4 v = *(const float4*)(x + e);
    v.x *= s; v.y *= s; v.z *= s; v.w *= s;
    *(float4*)(out + e) = v;
}

// ---------------- launcher ----------------
extern "C" void kernel_launch(void* const* d_in, const int* in_sizes, int n_in,
                              void* d_out, int out_size)
{
    const float* x = (const float*)d_in[0];
    float* out = (float*)d_out;

    float *A, *mean, *itr, *str, *cs;
    cudaGetSymbolAddress((void**)&A,    g_A);
    cudaGetSymbolAddress((void**)&mean, g_mean);
    cudaGetSymbolAddress((void**)&itr,  g_itr);
    cudaGetSymbolAddress((void**)&str,  g_str);
    cudaGetSymbolAddress((void**)&cs,   g_cs);

    cudaFuncSetAttribute(cov_gemm, cudaFuncAttributeMaxDynamicSharedMemorySize, GEMM_SMEM);

    // 1) row means
    mean_kernel<<<(B_*C_ + 7) / 8, 256>>>(x, mean);

    // 2) covariance (symmetric: 10 upper-tri tiles, write both halves)
    cov_gemm<<<dim3(10, 1, B_), GT, GEMM_SMEM>>>(x, A, mean);

    // 3) trace scalars
    trace_kernel<<<B_, 512>>>(A, itr, str);

    // 4) Newton-Schulz chain: 122 matvecs, single CTA per batch, MLP-optimized
    chain_kernel<<<B_, 1024>>>(A, itr, str, cs);

    // 5) out = cov_sum[b][c] * x
    const long total4 = (long)B_ * C_ * M_ / 4;
    scale_kernel<<<(int)((total4 + 255) / 256), 256>>>(x, cs, out);

    (void)in_sizes; (void)n_in; (void)out_size;
}

// round 7
// speedup vs baseline: 2.4412x; 2.4412x over previous
#include <cuda_runtime.h>
#include <math.h>
#include <stdint.h>

// Problem constants
#define B_  32
#define C_  512
#define M_  784            // 28*28
#define NSQ (C_*C_)        // 262144
#define NCTA 4             // CTAs per batch in the chain kernel

// ---------------- scratch ----------------
__device__ float    g_A [B_*NSQ];      // covariance matrices
__device__ float    g_mean[B_*C_];
__device__ float    g_itr[B_];         // 1/trace
__device__ float    g_str[B_];         // sqrt(trace)
__device__ float    g_cs [B_*C_];      // final column means
__device__ unsigned g_cnt[B_];         // per-batch arrival counters (zeroed by trace_kernel)
__device__ float    g_vbuf[B_][2][C_]; // double-buffered exchange vectors

// ================= warp-level tf32 MMA (sm_80 ISA) =================
__device__ __forceinline__ void mma_tf32(float* c, const uint32_t* a, const uint32_t* b) {
    asm volatile("mma.sync.aligned.m16n8k8.row.col.f32.tf32.tf32.f32 "
        "{%0,%1,%2,%3}, {%4,%5,%6,%7}, {%8,%9}, {%0,%1,%2,%3};"
        : "+f"(c[0]), "+f"(c[1]), "+f"(c[2]), "+f"(c[3])
        : "r"(a[0]), "r"(a[1]), "r"(a[2]), "r"(a[3]), "r"(b[0]), "r"(b[1]));
}
#define HI_MASK 0xFFFFE000u
__device__ __forceinline__ void split_tf32(float x, uint32_t& hi, uint32_t& lo) {
    uint32_t xb = __float_as_uint(x);
    hi = xb & HI_MASK;
    float lof = x - __uint_as_float(hi);
    lo = __float_as_uint(lof) & HI_MASK;
}

// ================= covariance GEMM (symmetric, upper-tri tiles only) =================
#define KCH  32
#define GT   256
#define APAD 36
#define ATILE_F (128*APAD)
#define STAGE_F (2*ATILE_F)
#define GEMM_SMEM (2*STAGE_F*4)   // 73728 bytes

__constant__ int c_bi[10] = {0,0,0,0,1,1,1,2,2,3};
__constant__ int c_bj[10] = {0,1,2,3,1,2,3,2,3,3};

__global__ void __launch_bounds__(GT)
cov_gemm(const float* __restrict__ xg, float* __restrict__ Cg,
         const float* __restrict__ meang)
{
    extern __shared__ float sm[];
    const int tid = threadIdx.x;
    const int b = blockIdx.z;
    const float* A  = xg + (long)b * C_ * M_;
    float*       C  = Cg + (long)b * NSQ;
    const int ib = c_bi[blockIdx.x] * 128;
    const int jb = c_bj[blockIdx.x] * 128;
    const int K = M_;
    const float covInvM = 1.0f / M_;

    const int wid = tid >> 5, lane = tid & 31;
    const int wm = wid & 1, wn = wid >> 1;
    const int gid = lane >> 2, tig = lane & 3;

    float acc[4][4][4];
    #pragma unroll
    for (int mf = 0; mf < 4; mf++)
        #pragma unroll
        for (int nf = 0; nf < 4; nf++)
            #pragma unroll
            for (int e = 0; e < 4; e++) acc[mf][nf][e] = 0.f;

    const int NC = (K + KCH - 1) / KCH;
    float4 ra[4], rb[4];

    #pragma unroll
    for (int q = 0; q < 4; q++) {
        int f = tid + q * GT; int r = f >> 3; int k = (f & 7) * 4;
        ra[q] = (k < K) ? *(const float4*)(A + (long)(ib + r) * M_ + k) : make_float4(0,0,0,0);
        rb[q] = (k < K) ? *(const float4*)(A + (long)(jb + r) * M_ + k) : make_float4(0,0,0,0);
    }
    #pragma unroll
    for (int q = 0; q < 4; q++) {
        int f = tid + q * GT; int r = f >> 3; int c = (f & 7) * 4;
        *(float4*)(sm + (long)r * APAD + c)           = ra[q];
        *(float4*)(sm + ATILE_F + (long)r * APAD + c) = rb[q];
    }
    __syncthreads();

    for (int i = 0; i < NC; i++) {
        if (i + 1 < NC) {
            const int k0 = (i + 1) * KCH;
            #pragma unroll
            for (int q = 0; q < 4; q++) {
                int f = tid + q * GT; int r = f >> 3; int k = k0 + (f & 7) * 4;
                ra[q] = (k < K) ? *(const float4*)(A + (long)(ib + r) * M_ + k) : make_float4(0,0,0,0);
                rb[q] = (k < K) ? *(const float4*)(A + (long)(jb + r) * M_ + k) : make_float4(0,0,0,0);
            }
        }
        const float* As = sm + (i & 1) * STAGE_F;
        const float* Bs = As + ATILE_F;
        #pragma unroll
        for (int ks = 0; ks < 4; ks++) {
            uint32_t ah[4][4], al[4][4];
            #pragma unroll
            for (int mf = 0; mf < 4; mf++) {
                int base = (wm * 64 + mf * 16 + gid) * APAD + ks * 8 + tig;
                split_tf32(As[base],                ah[mf][0], al[mf][0]);
                split_tf32(As[base + 8 * APAD],     ah[mf][1], al[mf][1]);
                split_tf32(As[base + 4],            ah[mf][2], al[mf][2]);
                split_tf32(As[base + 8 * APAD + 4], ah[mf][3], al[mf][3]);
            }
            uint32_t bh[4][2], bl[4][2];
            #pragma unroll
            for (int nf = 0; nf < 4; nf++) {
                int base = (wn * 32 + nf * 8 + gid) * APAD + ks * 8 + tig;
                split_tf32(Bs[base],     bh[nf][0], bl[nf][0]);
                split_tf32(Bs[base + 4], bh[nf][1], bl[nf][1]);
            }
            #pragma unroll
            for (int mf = 0; mf < 4; mf++)
                #pragma unroll
                for (int nf = 0; nf < 4; nf++) {
                    mma_tf32(acc[mf][nf], ah[mf], bh[nf]);
                    mma_tf32(acc[mf][nf], ah[mf], bl[nf]);
                    mma_tf32(acc[mf][nf], al[mf], bh[nf]);
                }
        }
        if (i + 1 < NC) {
            float* Ad = sm + ((i + 1) & 1) * STAGE_F;
            #pragma unroll
            for (int q = 0; q < 4; q++) {
                int f = tid + q * GT; int r = f >> 3; int c = (f & 7) * 4;
                *(float4*)(Ad + (long)r * APAD + c)           = ra[q];
                *(float4*)(Ad + ATILE_F + (long)r * APAD + c) = rb[q];
            }
        }
        __syncthreads();
    }

    const bool offdiag = (ib != jb);
    #pragma unroll
    for (int mf = 0; mf < 4; mf++) {
        const int row0 = ib + wm * 64 + mf * 16 + gid;
        float mi0 = meang[b * C_ + row0];
        float mi1 = meang[b * C_ + row0 + 8];
        #pragma unroll
        for (int nf = 0; nf < 4; nf++) {
            const int col0 = jb + wn * 32 + nf * 8 + tig * 2;
            float mj0 = meang[b * C_ + col0], mj1 = meang[b * C_ + col0 + 1];
            float c0 = acc[mf][nf][0] * covInvM - mi0 * mj0;
            float c1 = acc[mf][nf][1] * covInvM - mi0 * mj1;
            float c2 = acc[mf][nf][2] * covInvM - mi1 * mj0;
            float c3 = acc[mf][nf][3] * covInvM - mi1 * mj1;
            *(float2*)(C + (long)row0 * C_ + col0)       = make_float2(c0, c1);
            *(float2*)(C + (long)(row0 + 8) * C_ + col0) = make_float2(c2, c3);
            if (offdiag) {
                C[(long)col0 * C_ + row0]           = c0;
                C[(long)(col0 + 1) * C_ + row0]     = c1;
                C[(long)col0 * C_ + row0 + 8]       = c2;
                C[(long)(col0 + 1) * C_ + row0 + 8] = c3;
            }
        }
    }
}

// ---------------- per-row mean of x ----------------
__global__ void mean_kernel(const float* __restrict__ x, float* __restrict__ mean)
{
    int warp = (blockIdx.x * blockDim.x + threadIdx.x) >> 5;
    int lane = threadIdx.x & 31;
    if (warp >= B_*C_) return;
    const float* row = x + (long)warp * M_;
    float s = 0.f;
    for (int k = lane; k < M_; k += 32) s += row[k];
    #pragma unroll
    for (int off = 16; off; off >>= 1) s += __shfl_down_sync(0xffffffffu, s, off);
    if (lane == 0) mean[warp] = s * (1.0f / M_);
}

// ---------------- trace (also resets chain sync counters each launch) ----------------
__global__ void trace_kernel(const float* __restrict__ A,
                             float* __restrict__ itr, float* __restrict__ str)
{
    __shared__ float sh[512];
    const int b = blockIdx.x;
    const int i = threadIdx.x;
    if (i == 0) g_cnt[b] = 0u;
    sh[i] = A[(long)b * NSQ + (long)i * C_ + i];
    __syncthreads();
    for (int off = 256; off; off >>= 1) {
        if (i < off) sh[i] += sh[i + off];
        __syncthreads();
    }
    if (i == 0) { float t = sh[0]; itr[b] = 1.0f / t; str[b] = sqrtf(t); }
}

// ================= Newton-Schulz vector chain (4 CTAs per batch, global-flag sync) =================
// Ysqrt/sqrt(tr) = T * W0..W4, W_k = 1.5I - 0.5 S_k, S_0 = T, S_{k+1} = S_k W_k^2.
// 122 matvecs; each column-split over 4 CTAs; v exchanged via L2 (double-buffered) with
// atomic arrive counters. All combines done redundantly (identically) in each CTA.
struct Ctx {
    const float* Ab;
    float* v;          // smem full vector [512]
    float* partial;    // smem [16*128]
    float* p2;         // smem [4*128]
    float* vout;       // smem [128]
    float* pool;       // smem save stack [5*512]
    float  inv;
    int    tid;
    int    rank;
    int    step;
    unsigned* cnt;
    float* buf0;
    float* buf1;
};

// Distributed matvec: v_new = inv * (v^T A); this CTA computes cols [rank*128, +128).
__device__ void do_matvec(Ctx& c)
{
    const int j4 = c.tid & 31;          // 4-col group within our 128 columns
    const int isec = c.tid >> 5;        // 0..15, 32 rows each
    const float* base = c.Ab + (long)isec * 32 * C_ + c.rank * 128 + j4 * 4;
    const float* vs = c.v + isec * 32;

    float4 A0 = make_float4(0.f,0.f,0.f,0.f), A1 = A0, A2 = A0, A3 = A0;
    #pragma unroll
    for (int ii = 0; ii < 32; ii += 4) {
        float4 t0 = *(const float4*)(base + (long)(ii + 0) * C_);
        float4 t1 = *(const float4*)(base + (long)(ii + 1) * C_);
        float4 t2 = *(const float4*)(base + (long)(ii + 2) * C_);
        float4 t3 = *(const float4*)(base + (long)(ii + 3) * C_);
        float s0 = vs[ii + 0], s1 = vs[ii + 1], s2 = vs[ii + 2], s3 = vs[ii + 3];
        A0.x = fmaf(s0, t0.x, A0.x); A0.y = fmaf(s0, t0.y, A0.y);
        A0.z = fmaf(s0, t0.z, A0.z); A0.w = fmaf(s0, t0.w, A0.w);
        A1.x = fmaf(s1, t1.x, A1.x); A1.y = fmaf(s1, t1.y, A1.y);
        A1.z = fmaf(s1, t1.z, A1.z); A1.w = fmaf(s1, t1.w, A1.w);
        A2.x = fmaf(s2, t2.x, A2.x); A2.y = fmaf(s2, t2.y, A2.y);
        A2.z = fmaf(s2, t2.z, A2.z); A2.w = fmaf(s2, t2.w, A2.w);
        A3.x = fmaf(s3, t3.x, A3.x); A3.y = fmaf(s3, t3.y, A3.y);
        A3.z = fmaf(s3, t3.z, A3.z); A3.w = fmaf(s3, t3.w, A3.w);
    }
    A0.x += A1.x + A2.x + A3.x;
    A0.y += A1.y + A2.y + A3.y;
    A0.z += A1.z + A2.z + A3.z;
    A0.w += A1.w + A2.w + A3.w;
    *(float4*)(c.partial + isec * 128 + j4 * 4) = A0;
    __syncthreads();

    // two-stage reduce over 16 sections
    {
        int col = c.tid & 127, grp = c.tid >> 7;   // 4 groups of 4 sections
        float s = c.partial[(grp * 4 + 0) * 128 + col]
                + c.partial[(grp * 4 + 1) * 128 + col]
                + c.partial[(grp * 4 + 2) * 128 + col]
                + c.partial[(grp * 4 + 3) * 128 + col];
        c.p2[grp * 128 + col] = s;
    }
    __syncthreads();
    if (c.tid < 128) {
        float s = c.p2[c.tid] + c.p2[128 + c.tid] + c.p2[256 + c.tid] + c.p2[384 + c.tid];
        c.vout[c.tid] = s * c.inv;
    }
    __syncthreads();

    // publish our chunk, arrive, wait for all 4, reload full vector
    float* dst = (c.step & 1) ? c.buf1 : c.buf0;
    if (c.tid < 32)
        *(float4*)(dst + c.rank * 128 + c.tid * 4) = *(float4*)(c.vout + c.tid * 4);
    __threadfence();
    __syncthreads();
    if (c.tid == 0) {
        atomicAdd(c.cnt, 1u);
        const unsigned target = (unsigned)NCTA * (unsigned)(c.step + 1);
        volatile unsigned* p = c.cnt;
        while (*p < target) { }
    }
    __syncthreads();
    __threadfence();
    if (c.tid < 128) {
        float4 g = *(const float4*)(dst + c.tid * 4);
        *(float4*)(c.v + c.tid * 4) = g;
    }
    __syncthreads();
    c.step++;
}

__device__ void applyS(int k, Ctx& c, int sp);

__device__ void applyW(int k, Ctx& c, int sp)
{
    float* save = c.pool + sp * 512;
    if (c.tid < 512) save[c.tid] = c.v[c.tid];
    __syncthreads();
    applyS(k, c, sp + 1);
    if (c.tid < 512) c.v[c.tid] = 1.5f * save[c.tid] - 0.5f * c.v[c.tid];
    __syncthreads();
}

__device__ void applyS(int k, Ctx& c, int sp)
{
    if (k == 0) { do_matvec(c); return; }
    applyS(k - 1, c, sp);
    applyW(k - 1, c, sp);
    applyW(k - 1, c, sp);
}

__global__ void __launch_bounds__(512, 1)
chain_kernel(const float* __restrict__ A, const float* __restrict__ itr,
             const float* __restrict__ str, float* __restrict__ cs)
{
    __shared__ float v[512];
    __shared__ float partial[16 * 128];
    __shared__ float p2[4 * 128];
    __shared__ float vout[128];
    __shared__ float pool[5 * 512];
    const int tid = threadIdx.x;
    const int b = blockIdx.x >> 2;
    const int rank = blockIdx.x & 3;

    Ctx c;
    c.Ab = A + (long)b * NSQ;
    c.v = v; c.partial = partial; c.p2 = p2; c.vout = vout; c.pool = pool;
    c.inv = itr[b]; c.tid = tid; c.rank = rank; c.step = 0;
    c.cnt = &g_cnt[b];
    c.buf0 = &g_vbuf[b][0][0];
    c.buf1 = &g_vbuf[b][1][0];

    v[tid] = 1.0f;
    __syncthreads();

    do_matvec(c);                 // u = 1^T * T
    for (int k = 0; k < 5; k++)   // u = u * W_k
        applyW(k, c, 0);

    if (rank == 0)
        cs[b * C_ + tid] = v[tid] * str[b] * (1.0f / C_);
}

// ---------------- out = cov_sum * x ----------------
__global__ void scale_kernel(const float* __restrict__ x,
                             const float* __restrict__ cs, float* __restrict__ out)
{
    long i4 = (long)blockIdx.x * blockDim.x + threadIdx.x;
    const long total4 = (long)B_ * C_ * M_ / 4;
    if (i4 >= total4) return;
    long e = i4 * 4;
    int bc = (int)(e / M_);
    float s = cs[bc];
    float4 v = *(const float4*)(x + e);
    v.x *= s; v.y *= s; v.z *= s; v.w *= s;
    *(float4*)(out + e) = v;
}

// ---------------- launcher ----------------
extern "C" void kernel_launch(void* const* d_in, const int* in_sizes, int n_in,
                              void* d_out, int out_size)
{
    const float* x = (const float*)d_in[0];
    float* out = (float*)d_out;

    float *A, *mean, *itr, *str, *cs;
    cudaGetSymbolAddress((void**)&A,    g_A);
    cudaGetSymbolAddress((void**)&mean, g_mean);
    cudaGetSymbolAddress((void**)&itr,  g_itr);
    cudaGetSymbolAddress((void**)&str,  g_str);
    cudaGetSymbolAddress((void**)&cs,   g_cs);

    cudaFuncSetAttribute(cov_gemm, cudaFuncAttributeMaxDynamicSharedMemorySize, GEMM_SMEM);

    // 1) row means
    mean_kernel<<<(B_*C_ + 7) / 8, 256>>>(x, mean);

    // 2) covariance (symmetric: 10 upper-tri tiles, write both halves)
    cov_gemm<<<dim3(10, 1, B_), GT, GEMM_SMEM>>>(x, A, mean);

    // 3) trace scalars + chain counter reset
    trace_kernel<<<B_, 512>>>(A, itr, str);

    // 4) Newton-Schulz chain: 122 matvecs, 4 CTAs per batch, global-flag sync
    chain_kernel<<<B_ * NCTA, 512>>>(A, itr, str, cs);

    // 5) out = cov_sum[b][c] * x
    const long total4 = (long)B_ * C_ * M_ / 4;
    scale_kernel<<<(int)((total4 + 255) / 256), 256>>>(x, cs, out);

    (void)in_sizes; (void)n_in; (void)out_size;
}

// round 8
// speedup vs baseline: 2.5915x; 1.0616x over previous
#include <cuda_runtime.h>
#include <math.h>
#include <stdint.h>

// Problem constants
#define B_  32
#define C_  512
#define M_  784            // 28*28
#define NSQ (C_*C_)        // 262144
#define NCTA 4             // CTAs per batch in the chain kernel

// ---------------- scratch ----------------
__device__ float    g_A [B_*NSQ];      // covariance matrices
__device__ float    g_mean[B_*C_];
__device__ float    g_itr[B_];         // 1/trace
__device__ float    g_str[B_];         // sqrt(trace)
__device__ float    g_cs [B_*C_];      // final column means
__device__ unsigned g_flag[B_][NCTA][32];  // per-(batch,rank) seq flags, 128B apart
__device__ float    g_ubuf[B_][2][C_];     // double-buffered raw matvec exchange

// ================= warp-level tf32 MMA (sm_80 ISA) =================
__device__ __forceinline__ void mma_tf32(float* c, const uint32_t* a, const uint32_t* b) {
    asm volatile("mma.sync.aligned.m16n8k8.row.col.f32.tf32.tf32.f32 "
        "{%0,%1,%2,%3}, {%4,%5,%6,%7}, {%8,%9}, {%0,%1,%2,%3};"
        : "+f"(c[0]), "+f"(c[1]), "+f"(c[2]), "+f"(c[3])
        : "r"(a[0]), "r"(a[1]), "r"(a[2]), "r"(a[3]), "r"(b[0]), "r"(b[1]));
}
#define HI_MASK 0xFFFFE000u
__device__ __forceinline__ void split_tf32(float x, uint32_t& hi, uint32_t& lo) {
    uint32_t xb = __float_as_uint(x);
    hi = xb & HI_MASK;
    float lof = x - __uint_as_float(hi);
    lo = __float_as_uint(lof) & HI_MASK;
}

// ================= covariance GEMM (symmetric, upper-tri tiles only) =================
#define KCH  32
#define GT   256
#define APAD 36
#define ATILE_F (128*APAD)
#define STAGE_F (2*ATILE_F)
#define GEMM_SMEM (2*STAGE_F*4)   // 73728 bytes

__constant__ int c_bi[10] = {0,0,0,0,1,1,1,2,2,3};
__constant__ int c_bj[10] = {0,1,2,3,1,2,3,2,3,3};

__global__ void __launch_bounds__(GT)
cov_gemm(const float* __restrict__ xg, float* __restrict__ Cg,
         const float* __restrict__ meang)
{
    extern __shared__ float sm[];
    const int tid = threadIdx.x;
    const int b = blockIdx.z;
    const float* A  = xg + (long)b * C_ * M_;
    float*       C  = Cg + (long)b * NSQ;
    const int ib = c_bi[blockIdx.x] * 128;
    const int jb = c_bj[blockIdx.x] * 128;
    const int K = M_;
    const float covInvM = 1.0f / M_;

    const int wid = tid >> 5, lane = tid & 31;
    const int wm = wid & 1, wn = wid >> 1;
    const int gid = lane >> 2, tig = lane & 3;

    float acc[4][4][4];
    #pragma unroll
    for (int mf = 0; mf < 4; mf++)
        #pragma unroll
        for (int nf = 0; nf < 4; nf++)
            #pragma unroll
            for (int e = 0; e < 4; e++) acc[mf][nf][e] = 0.f;

    const int NC = (K + KCH - 1) / KCH;
    float4 ra[4], rb[4];

    #pragma unroll
    for (int q = 0; q < 4; q++) {
        int f = tid + q * GT; int r = f >> 3; int k = (f & 7) * 4;
        ra[q] = (k < K) ? *(const float4*)(A + (long)(ib + r) * M_ + k) : make_float4(0,0,0,0);
        rb[q] = (k < K) ? *(const float4*)(A + (long)(jb + r) * M_ + k) : make_float4(0,0,0,0);
    }
    #pragma unroll
    for (int q = 0; q < 4; q++) {
        int f = tid + q * GT; int r = f >> 3; int c = (f & 7) * 4;
        *(float4*)(sm + (long)r * APAD + c)           = ra[q];
        *(float4*)(sm + ATILE_F + (long)r * APAD + c) = rb[q];
    }
    __syncthreads();

    for (int i = 0; i < NC; i++) {
        if (i + 1 < NC) {
            const int k0 = (i + 1) * KCH;
            #pragma unroll
            for (int q = 0; q < 4; q++) {
                int f = tid + q * GT; int r = f >> 3; int k = k0 + (f & 7) * 4;
                ra[q] = (k < K) ? *(const float4*)(A + (long)(ib + r) * M_ + k) : make_float4(0,0,0,0);
                rb[q] = (k < K) ? *(const float4*)(A + (long)(jb + r) * M_ + k) : make_float4(0,0,0,0);
            }
        }
        const float* As = sm + (i & 1) * STAGE_F;
        const float* Bs = As + ATILE_F;
        #pragma unroll
        for (int ks = 0; ks < 4; ks++) {
            uint32_t ah[4][4], al[4][4];
            #pragma unroll
            for (int mf = 0; mf < 4; mf++) {
                int base = (wm * 64 + mf * 16 + gid) * APAD + ks * 8 + tig;
                split_tf32(As[base],                ah[mf][0], al[mf][0]);
                split_tf32(As[base + 8 * APAD],     ah[mf][1], al[mf][1]);
                split_tf32(As[base + 4],            ah[mf][2], al[mf][2]);
                split_tf32(As[base + 8 * APAD + 4], ah[mf][3], al[mf][3]);
            }
            uint32_t bh[4][2], bl[4][2];
            #pragma unroll
            for (int nf = 0; nf < 4; nf++) {
                int base = (wn * 32 + nf * 8 + gid) * APAD + ks * 8 + tig;
                split_tf32(Bs[base],     bh[nf][0], bl[nf][0]);
                split_tf32(Bs[base + 4], bh[nf][1], bl[nf][1]);
            }
            #pragma unroll
            for (int mf = 0; mf < 4; mf++)
                #pragma unroll
                for (int nf = 0; nf < 4; nf++) {
                    mma_tf32(acc[mf][nf], ah[mf], bh[nf]);
                    mma_tf32(acc[mf][nf], ah[mf], bl[nf]);
                    mma_tf32(acc[mf][nf], al[mf], bh[nf]);
                }
        }
        if (i + 1 < NC) {
            float* Ad = sm + ((i + 1) & 1) * STAGE_F;
            #pragma unroll
            for (int q = 0; q < 4; q++) {
                int f = tid + q * GT; int r = f >> 3; int c = (f & 7) * 4;
                *(float4*)(Ad + (long)r * APAD + c)           = ra[q];
                *(float4*)(Ad + ATILE_F + (long)r * APAD + c) = rb[q];
            }
        }
        __syncthreads();
    }

    const bool offdiag = (ib != jb);
    #pragma unroll
    for (int mf = 0; mf < 4; mf++) {
        const int row0 = ib + wm * 64 + mf * 16 + gid;
        float mi0 = meang[b * C_ + row0];
        float mi1 = meang[b * C_ + row0 + 8];
        #pragma unroll
        for (int nf = 0; nf < 4; nf++) {
            const int col0 = jb + wn * 32 + nf * 8 + tig * 2;
            float mj0 = meang[b * C_ + col0], mj1 = meang[b * C_ + col0 + 1];
            float c0 = acc[mf][nf][0] * covInvM - mi0 * mj0;
            float c1 = acc[mf][nf][1] * covInvM - mi0 * mj1;
            float c2 = acc[mf][nf][2] * covInvM - mi1 * mj0;
            float c3 = acc[mf][nf][3] * covInvM - mi1 * mj1;
            *(float2*)(C + (long)row0 * C_ + col0)       = make_float2(c0, c1);
            *(float2*)(C + (long)(row0 + 8) * C_ + col0) = make_float2(c2, c3);
            if (offdiag) {
                C[(long)col0 * C_ + row0]           = c0;
                C[(long)(col0 + 1) * C_ + row0]     = c1;
                C[(long)col0 * C_ + row0 + 8]       = c2;
                C[(long)(col0 + 1) * C_ + row0 + 8] = c3;
            }
        }
    }
}

// ---------------- per-row mean of x ----------------
__global__ void mean_kernel(const float* __restrict__ x, float* __restrict__ mean)
{
    int warp = (blockIdx.x * blockDim.x + threadIdx.x) >> 5;
    int lane = threadIdx.x & 31;
    if (warp >= B_*C_) return;
    const float* row = x + (long)warp * M_;
    float s = 0.f;
    for (int k = lane; k < M_; k += 32) s += row[k];
    #pragma unroll
    for (int off = 16; off; off >>= 1) s += __shfl_down_sync(0xffffffffu, s, off);
    if (lane == 0) mean[warp] = s * (1.0f / M_);
}

// ---------------- trace (also resets chain flags each launch) ----------------
__global__ void trace_kernel(const float* __restrict__ A,
                             float* __restrict__ itr, float* __restrict__ str)
{
    __shared__ float sh[512];
    const int b = blockIdx.x;
    const int i = threadIdx.x;
    if (i < NCTA) g_flag[b][i][0] = 0u;
    sh[i] = A[(long)b * NSQ + (long)i * C_ + i];
    __syncthreads();
    for (int off = 256; off; off >>= 1) {
        if (i < off) sh[i] += sh[i + off];
        __syncthreads();
    }
    if (i == 0) { float t = sh[0]; itr[b] = 1.0f / t; str[b] = sqrtf(t); }
}

// ================= Newton-Schulz vector chain =================
// 122 matvecs; each column-split over 4 CTAs; raw chunk exchanged via L2 with
// per-rank release/acquire sequence flags (each flag on its own 128B line).
__device__ __forceinline__ unsigned ld_acq(const unsigned* p) {
    unsigned v;
    asm volatile("ld.acquire.gpu.global.u32 %0, [%1];" : "=r"(v) : "l"(p) : "memory");
    return v;
}
__device__ __forceinline__ void st_rel(unsigned* p, unsigned v) {
    asm volatile("st.release.gpu.global.u32 [%0], %1;" :: "l"(p), "r"(v) : "memory");
}

struct Ctx {
    const float* Ab;
    float* v;          // smem full vector [512]
    float* partial;    // smem [16*128]
    float* p2;         // smem [4*128]
    float* vout;       // smem [128]
    float* pool;       // smem save stack [5*512]
    float  inv;
    int    tid;
    int    rank;
    int    step;       // matvec counter
    int    b;
};

// Distributed matvec: raw u = v^T A * inv; this CTA computes cols [rank*128, +128).
__device__ void do_matvec(Ctx& c)
{
    const int j4 = c.tid & 31;          // 4-col group within our 128 columns
    const int isec = c.tid >> 5;        // 0..15, 32 rows each
    const float* base = c.Ab + (long)isec * 32 * C_ + c.rank * 128 + j4 * 4;
    const float* vs = c.v + isec * 32;

    float4 A0 = make_float4(0.f,0.f,0.f,0.f), A1 = A0, A2 = A0, A3 = A0;
    #pragma unroll
    for (int ii = 0; ii < 32; ii += 4) {
        float4 t0 = *(const float4*)(base + (long)(ii + 0) * C_);
        float4 t1 = *(const float4*)(base + (long)(ii + 1) * C_);
        float4 t2 = *(const float4*)(base + (long)(ii + 2) * C_);
        float4 t3 = *(const float4*)(base + (long)(ii + 3) * C_);
        float s0 = vs[ii + 0], s1 = vs[ii + 1], s2 = vs[ii + 2], s3 = vs[ii + 3];
        A0.x = fmaf(s0, t0.x, A0.x); A0.y = fmaf(s0, t0.y, A0.y);
        A0.z = fmaf(s0, t0.z, A0.z); A0.w = fmaf(s0, t0.w, A0.w);
        A1.x = fmaf(s1, t1.x, A1.x); A1.y = fmaf(s1, t1.y, A1.y);
        A1.z = fmaf(s1, t1.z, A1.z); A1.w = fmaf(s1, t1.w, A1.w);
        A2.x = fmaf(s2, t2.x, A2.x); A2.y = fmaf(s2, t2.y, A2.y);
        A2.z = fmaf(s2, t2.z, A2.z); A2.w = fmaf(s2, t2.w, A2.w);
        A3.x = fmaf(s3, t3.x, A3.x); A3.y = fmaf(s3, t3.y, A3.y);
        A3.z = fmaf(s3, t3.z, A3.z); A3.w = fmaf(s3, t3.w, A3.w);
    }
    A0.x += A1.x + A2.x + A3.x;
    A0.y += A1.y + A2.y + A3.y;
    A0.z += A1.z + A2.z + A3.z;
    A0.w += A1.w + A2.w + A3.w;
    *(float4*)(c.partial + isec * 128 + j4 * 4) = A0;
    __syncthreads();

    // two-stage reduce over 16 sections
    {
        int col = c.tid & 127, grp = c.tid >> 7;
        float s = c.partial[(grp * 4 + 0) * 128 + col]
                + c.partial[(grp * 4 + 1) * 128 + col]
                + c.partial[(grp * 4 + 2) * 128 + col]
                + c.partial[(grp * 4 + 3) * 128 + col];
        c.p2[grp * 128 + col] = s;
    }
    __syncthreads();
    if (c.tid < 128) {
        float s = c.p2[c.tid] + c.p2[128 + c.tid] + c.p2[256 + c.tid] + c.p2[384 + c.tid];
        c.vout[c.tid] = s * c.inv;
    }
    __syncthreads();

    // publish our chunk (plain STG), then release-store our flag
    float* dst = &g_ubuf[c.b][c.step & 1][0];
    if (c.tid < 32)
        *(float4*)(dst + c.rank * 128 + c.tid * 4) = *(float4*)(c.vout + c.tid * 4);
    __syncthreads();
    const unsigned target = (unsigned)(c.step + 1);
    if (c.tid == 0)
        st_rel(&g_flag[c.b][c.rank][0], target);

    // poll 3 peer flags in parallel (acquire), one thread each
    if (c.tid >= 1 && c.tid <= 3) {
        int peer = (c.rank + c.tid) & 3;
        const unsigned* pf = &g_flag[c.b][peer][0];
        while (ld_acq(pf) < target) { }
    }
    __syncthreads();

    // gather full raw vector into v (L2 loads, bypass L1)
    if (c.tid < 128) {
        float4 g = __ldcg((const float4*)(dst + c.tid * 4));
        *(float4*)(c.v + c.tid * 4) = g;
    }
    __syncthreads();
    c.step++;
}

__device__ void applyS(int k, Ctx& c, int sp);

__device__ void applyW(int k, Ctx& c, int sp)
{
    float* save = c.pool + sp * 512;
    save[c.tid] = c.v[c.tid];
    __syncthreads();
    applyS(k, c, sp + 1);
    c.v[c.tid] = 1.5f * save[c.tid] - 0.5f * c.v[c.tid];
    __syncthreads();
}

__device__ void applyS(int k, Ctx& c, int sp)
{
    if (k == 0) { do_matvec(c); return; }
    applyS(k - 1, c, sp);
    applyW(k - 1, c, sp);
    applyW(k - 1, c, sp);
}

__global__ void __launch_bounds__(512, 1)
chain_kernel(const float* __restrict__ A, const float* __restrict__ itr,
             const float* __restrict__ str, float* __restrict__ cs)
{
    __shared__ float v[512];
    __shared__ float partial[16 * 128];
    __shared__ float p2[4 * 128];
    __shared__ float vout[128];
    __shared__ float pool[5 * 512];
    const int tid = threadIdx.x;
    const int b = blockIdx.x >> 2;
    const int rank = blockIdx.x & 3;

    Ctx c;
    c.Ab = A + (long)b * NSQ;
    c.v = v; c.partial = partial; c.p2 = p2; c.vout = vout; c.pool = pool;
    c.inv = itr[b]; c.tid = tid; c.rank = rank; c.step = 0; c.b = b;

    v[tid] = 1.0f;
    __syncthreads();

    do_matvec(c);                 // u = 1^T * T
    for (int k = 0; k < 5; k++)   // u = u * W_k
        applyW(k, c, 0);

    if (rank == 0)
        cs[b * C_ + tid] = v[tid] * str[b] * (1.0f / C_);
}

// ---------------- out = cov_sum * x ----------------
__global__ void scale_kernel(const float* __restrict__ x,
                             const float* __restrict__ cs, float* __restrict__ out)
{
    long i4 = (long)blockIdx.x * blockDim.x + threadIdx.x;
    const long total4 = (long)B_ * C_ * M_ / 4;
    if (i4 >= total4) return;
    long e = i4 * 4;
    int bc = (int)(e / M_);
    float s = cs[bc];
    float4 v = *(const float4*)(x + e);
    v.x *= s; v.y *= s; v.z *= s; v.w *= s;
    *(float4*)(out + e) = v;
}

// ---------------- launcher ----------------
extern "C" void kernel_launch(void* const* d_in, const int* in_sizes, int n_in,
                              void* d_out, int out_size)
{
    const float* x = (const float*)d_in[0];
    float* out = (float*)d_out;

    float *A, *mean, *itr, *str, *cs;
    cudaGetSymbolAddress((void**)&A,    g_A);
    cudaGetSymbolAddress((void**)&mean, g_mean);
    cudaGetSymbolAddress((void**)&itr,  g_itr);
    cudaGetSymbolAddress((void**)&str,  g_str);
    cudaGetSymbolAddress((void**)&cs,   g_cs);

    cudaFuncSetAttribute(cov_gemm, cudaFuncAttributeMaxDynamicSharedMemorySize, GEMM_SMEM);

    // 1) row means
    mean_kernel<<<(B_*C_ + 7) / 8, 256>>>(x, mean);

    // 2) covariance (symmetric: 10 upper-tri tiles, write both halves)
    cov_gemm<<<dim3(10, 1, B_), GT, GEMM_SMEM>>>(x, A, mean);

    // 3) trace scalars + chain flag reset
    trace_kernel<<<B_, 512>>>(A, itr, str);

    // 4) Newton-Schulz chain: 122 matvecs, 4 CTAs/batch, release/acquire flags
    chain_kernel<<<B_ * NCTA, 512>>>(A, itr, str, cs);

    // 5) out = cov_sum[b][c] * x
    const long total4 = (long)B_ * C_ * M_ / 4;
    scale_kernel<<<(int)((total4 + 255) / 256), 256>>>(x, cs, out);

    (void)in_sizes; (void)n_in; (void)out_size;
}

// round 10
// speedup vs baseline: 3.0472x; 1.1759x over previous
#include <cuda_runtime.h>
#include <math.h>
#include <stdint.h>

// Problem constants
#define B_  32
#define C_  512
#define M_  784            // 28*28
#define NSQ (C_*C_)        // 262144

// ---------------- scratch ----------------
__device__ float g_A [B_*NSQ];   // covariance matrices
__device__ float g_mean[B_*C_];
__device__ float g_itr[B_];      // 1/trace
__device__ float g_str[B_];      // sqrt(trace)
__device__ float g_cs [B_*C_];   // final column means

// ================= warp-level tf32 MMA (sm_80 ISA) =================
__device__ __forceinline__ void mma_tf32(float* c, const uint32_t* a, const uint32_t* b) {
    asm volatile("mma.sync.aligned.m16n8k8.row.col.f32.tf32.tf32.f32 "
        "{%0,%1,%2,%3}, {%4,%5,%6,%7}, {%8,%9}, {%0,%1,%2,%3};"
        : "+f"(c[0]), "+f"(c[1]), "+f"(c[2]), "+f"(c[3])
        : "r"(a[0]), "r"(a[1]), "r"(a[2]), "r"(a[3]), "r"(b[0]), "r"(b[1]));
}
#define HI_MASK 0xFFFFE000u
__device__ __forceinline__ void split_tf32(float x, uint32_t& hi, uint32_t& lo) {
    uint32_t xb = __float_as_uint(x);
    hi = xb & HI_MASK;
    float lof = x - __uint_as_float(hi);
    lo = __float_as_uint(lof) & HI_MASK;
}

// ================= covariance GEMM (symmetric, upper-tri tiles only) =================
#define KCH  32
#define GT   256
#define APAD 36
#define ATILE_F (128*APAD)
#define STAGE_F (2*ATILE_F)
#define GEMM_SMEM (2*STAGE_F*4)   // 73728 bytes

__constant__ int c_bi[10] = {0,0,0,0,1,1,1,2,2,3};
__constant__ int c_bj[10] = {0,1,2,3,1,2,3,2,3,3};

__global__ void __launch_bounds__(GT)
cov_gemm(const float* __restrict__ xg, float* __restrict__ Cg,
         const float* __restrict__ meang)
{
    extern __shared__ float sm[];
    const int tid = threadIdx.x;
    const int b = blockIdx.z;
    const float* A  = xg + (long)b * C_ * M_;
    float*       C  = Cg + (long)b * NSQ;
    const int ib = c_bi[blockIdx.x] * 128;
    const int jb = c_bj[blockIdx.x] * 128;
    const int K = M_;
    const float covInvM = 1.0f / M_;

    const int wid = tid >> 5, lane = tid & 31;
    const int wm = wid & 1, wn = wid >> 1;
    const int gid = lane >> 2, tig = lane & 3;

    float acc[4][4][4];
    #pragma unroll
    for (int mf = 0; mf < 4; mf++)
        #pragma unroll
        for (int nf = 0; nf < 4; nf++)
            #pragma unroll
            for (int e = 0; e < 4; e++) acc[mf][nf][e] = 0.f;

    const int NC = (K + KCH - 1) / KCH;
    float4 ra[4], rb[4];

    #pragma unroll
    for (int q = 0; q < 4; q++) {
        int f = tid + q * GT; int r = f >> 3; int k = (f & 7) * 4;
        ra[q] = (k < K) ? *(const float4*)(A + (long)(ib + r) * M_ + k) : make_float4(0,0,0,0);
        rb[q] = (k < K) ? *(const float4*)(A + (long)(jb + r) * M_ + k) : make_float4(0,0,0,0);
    }
    #pragma unroll
    for (int q = 0; q < 4; q++) {
        int f = tid + q * GT; int r = f >> 3; int c = (f & 7) * 4;
        *(float4*)(sm + (long)r * APAD + c)           = ra[q];
        *(float4*)(sm + ATILE_F + (long)r * APAD + c) = rb[q];
    }
    __syncthreads();

    for (int i = 0; i < NC; i++) {
        if (i + 1 < NC) {
            const int k0 = (i + 1) * KCH;
            #pragma unroll
            for (int q = 0; q < 4; q++) {
                int f = tid + q * GT; int r = f >> 3; int k = k0 + (f & 7) * 4;
                ra[q] = (k < K) ? *(const float4*)(A + (long)(ib + r) * M_ + k) : make_float4(0,0,0,0);
                rb[q] = (k < K) ? *(const float4*)(A + (long)(jb + r) * M_ + k) : make_float4(0,0,0,0);
            }
        }
        const float* As = sm + (i & 1) * STAGE_F;
        const float* Bs = As + ATILE_F;
        #pragma unroll
        for (int ks = 0; ks < 4; ks++) {
            uint32_t ah[4][4], al[4][4];
            #pragma unroll
            for (int mf = 0; mf < 4; mf++) {
                int base = (wm * 64 + mf * 16 + gid) * APAD + ks * 8 + tig;
                split_tf32(As[base],                ah[mf][0], al[mf][0]);
                split_tf32(As[base + 8 * APAD],     ah[mf][1], al[mf][1]);
                split_tf32(As[base + 4],            ah[mf][2], al[mf][2]);
                split_tf32(As[base + 8 * APAD + 4], ah[mf][3], al[mf][3]);
            }
            uint32_t bh[4][2], bl[4][2];
            #pragma unroll
            for (int nf = 0; nf < 4; nf++) {
                int base = (wn * 32 + nf * 8 + gid) * APAD + ks * 8 + tig;
                split_tf32(Bs[base],     bh[nf][0], bl[nf][0]);
                split_tf32(Bs[base + 4], bh[nf][1], bl[nf][1]);
            }
            #pragma unroll
            for (int mf = 0; mf < 4; mf++)
                #pragma unroll
                for (int nf = 0; nf < 4; nf++) {
                    mma_tf32(acc[mf][nf], ah[mf], bh[nf]);
                    mma_tf32(acc[mf][nf], ah[mf], bl[nf]);
                    mma_tf32(acc[mf][nf], al[mf], bh[nf]);
                }
        }
        if (i + 1 < NC) {
            float* Ad = sm + ((i + 1) & 1) * STAGE_F;
            #pragma unroll
            for (int q = 0; q < 4; q++) {
                int f = tid + q * GT; int r = f >> 3; int c = (f & 7) * 4;
                *(float4*)(Ad + (long)r * APAD + c)           = ra[q];
                *(float4*)(Ad + ATILE_F + (long)r * APAD + c) = rb[q];
            }
        }
        __syncthreads();
    }

    const bool offdiag = (ib != jb);
    #pragma unroll
    for (int mf = 0; mf < 4; mf++) {
        const int row0 = ib + wm * 64 + mf * 16 + gid;
        float mi0 = meang[b * C_ + row0];
        float mi1 = meang[b * C_ + row0 + 8];
        #pragma unroll
        for (int nf = 0; nf < 4; nf++) {
            const int col0 = jb + wn * 32 + nf * 8 + tig * 2;
            float mj0 = meang[b * C_ + col0], mj1 = meang[b * C_ + col0 + 1];
            float c0 = acc[mf][nf][0] * covInvM - mi0 * mj0;
            float c1 = acc[mf][nf][1] * covInvM - mi0 * mj1;
            float c2 = acc[mf][nf][2] * covInvM - mi1 * mj0;
            float c3 = acc[mf][nf][3] * covInvM - mi1 * mj1;
            *(float2*)(C + (long)row0 * C_ + col0)       = make_float2(c0, c1);
            *(float2*)(C + (long)(row0 + 8) * C_ + col0) = make_float2(c2, c3);
            if (offdiag) {
                C[(long)col0 * C_ + row0]           = c0;
                C[(long)(col0 + 1) * C_ + row0]     = c1;
                C[(long)col0 * C_ + row0 + 8]       = c2;
                C[(long)(col0 + 1) * C_ + row0 + 8] = c3;
            }
        }
    }
}

// ---------------- per-row mean of x ----------------
__global__ void mean_kernel(const float* __restrict__ x, float* __restrict__ mean)
{
    int warp = (blockIdx.x * blockDim.x + threadIdx.x) >> 5;
    int lane = threadIdx.x & 31;
    if (warp >= B_*C_) return;
    const float* row = x + (long)warp * M_;
    float s = 0.f;
    for (int k = lane; k < M_; k += 32) s += row[k];
    #pragma unroll
    for (int off = 16; off; off >>= 1) s += __shfl_down_sync(0xffffffffu, s, off);
    if (lane == 0) mean[warp] = s * (1.0f / M_);
}

// ---------------- trace ----------------
__global__ void trace_kernel(const float* __restrict__ A,
                             float* __restrict__ itr, float* __restrict__ str)
{
    __shared__ float sh[512];
    const int b = blockIdx.x;
    const int i = threadIdx.x;
    sh[i] = A[(long)b * NSQ + (long)i * C_ + i];
    __syncthreads();
    for (int off = 256; off; off >>= 1) {
        if (i < off) sh[i] += sh[i + off];
        __syncthreads();
    }
    if (i == 0) { float t = sh[0]; itr[b] = 1.0f / t; str[b] = sqrtf(t); }
}

// ================= Newton-Schulz vector chain (single CTA, iterative driver) =================
// Ysqrt/sqrt(tr) = T * W0..W4, W_k = 1.5I - 0.5 S_k, S_0 = T, S_{k+1} = S_k W_k^2.
// 122 sequential matvecs, driven by an explicit state machine (no device recursion).
struct ChainCtx {
    const float* Ab;
    float* v;          // smem current vector [512]
    float* partial;    // smem [2*512]
    float* pool;       // smem save stack [5*512]
    float  inv;
    int    tid;
};

// Thread t owns column t&511 and row-half t>>9: warp reads one 128B line per
// row (1 wavefront), v[i] is an LDS broadcast, reduction = one 2-way add.
__device__ void do_matvec(ChainCtx& c)
{
    const int col  = c.tid & 511;
    const int half = c.tid >> 9;
    const float* base = c.Ab + (long)half * 256 * C_ + col;
    const float* vs = c.v + half * 256;

    float a0 = 0.f, a1 = 0.f, a2 = 0.f, a3 = 0.f;
    #pragma unroll
    for (int i = 0; i < 256; i += 8) {
        float t0 = base[(long)(i + 0) * C_];
        float t1 = base[(long)(i + 1) * C_];
        float t2 = base[(long)(i + 2) * C_];
        float t3 = base[(long)(i + 3) * C_];
        float t4 = base[(long)(i + 4) * C_];
        float t5 = base[(long)(i + 5) * C_];
        float t6 = base[(long)(i + 6) * C_];
        float t7 = base[(long)(i + 7) * C_];
        float s0 = vs[i + 0], s1 = vs[i + 1], s2 = vs[i + 2], s3 = vs[i + 3];
        float s4 = vs[i + 4], s5 = vs[i + 5], s6 = vs[i + 6], s7 = vs[i + 7];
        a0 = fmaf(s0, t0, a0);
        a1 = fmaf(s1, t1, a1);
        a2 = fmaf(s2, t2, a2);
        a3 = fmaf(s3, t3, a3);
        a0 = fmaf(s4, t4, a0);
        a1 = fmaf(s5, t5, a1);
        a2 = fmaf(s6, t6, a2);
        a3 = fmaf(s7, t7, a3);
    }
    c.partial[half * 512 + col] = (a0 + a1) + (a2 + a3);
    __syncthreads();
    if (c.tid < 512)
        c.v[c.tid] = (c.partial[c.tid] + c.partial[512 + c.tid]) * c.inv;
    __syncthreads();
}

// Iterative execution of applyW(k0, sp=0):
//   W(k,sp): save(sp); S(k, sp+1); v = 1.5*save - 0.5*v
//   S(k,sp): k==0 ? matvec : { S(k-1,sp); W(k-1,sp); W(k-1,sp); }
// Frames: ty 0=W, 1=S; st = resume stage. Depth <= 12. Uniform control flow.
__device__ void exec_W(int k0, ChainCtx& c)
{
    int ty[16], kk[16], sp[16], st[16];
    int top = 0;
    ty[0] = 0; kk[0] = k0; sp[0] = 0; st[0] = 0; top = 1;
    while (top > 0) {
        const int i = top - 1;
        if (ty[i] == 0) {                       // W frame
            if (st[i] == 0) {
                float* save = c.pool + sp[i] * 512;
                if (c.tid < 512) save[c.tid] = c.v[c.tid];
                __syncthreads();
                st[i] = 1;
                ty[top] = 1; kk[top] = kk[i]; sp[top] = sp[i] + 1; st[top] = 0; top++;
            } else {
                float* save = c.pool + sp[i] * 512;
                if (c.tid < 512) c.v[c.tid] = 1.5f * save[c.tid] - 0.5f * c.v[c.tid];
                __syncthreads();
                top--;
            }
        } else {                                // S frame
            if (kk[i] == 0) { do_matvec(c); top--; }
            else if (st[i] == 0) {
                st[i] = 1;
                ty[top] = 1; kk[top] = kk[i] - 1; sp[top] = sp[i]; st[top] = 0; top++;
            } else if (st[i] == 1) {
                st[i] = 2;
                ty[top] = 0; kk[top] = kk[i] - 1; sp[top] = sp[i]; st[top] = 0; top++;
            } else if (st[i] == 2) {
                st[i] = 3;
                ty[top] = 0; kk[top] = kk[i] - 1; sp[top] = sp[i]; st[top] = 0; top++;
            } else top--;
        }
    }
}

__global__ void __launch_bounds__(1024, 1)
chain_kernel(const float* __restrict__ A, const float* __restrict__ itr,
             const float* __restrict__ str, float* __restrict__ cs)
{
    __shared__ float v[512];
    __shared__ float partial[2 * 512];
    __shared__ float pool[5 * 512];
    const int b = blockIdx.x;
    const int tid = threadIdx.x;

    ChainCtx c;
    c.Ab = A + (long)b * NSQ;
    c.v = v; c.partial = partial; c.pool = pool;
    c.inv = itr[b]; c.tid = tid;

    if (tid < 512) v[tid] = 1.0f;
    __syncthreads();

    do_matvec(c);                 // u = 1^T * T
    for (int k = 0; k < 5; k++)   // u = u * W_k
        exec_W(k, c);

    if (tid < 512) cs[b * C_ + tid] = v[tid] * str[b] * (1.0f / C_);
}

// ---------------- out = cov_sum * x ----------------
__global__ void scale_kernel(const float* __restrict__ x,
                             const float* __restrict__ cs, float* __restrict__ out)
{
    long i4 = (long)blockIdx.x * blockDim.x + threadIdx.x;
    const long total4 = (long)B_ * C_ * M_ / 4;
    if (i4 >= total4) return;
    long e = i4 * 4;
    int bc = (int)(e / M_);
    float s = cs[bc];
    float4 v = *(const float4*)(x + e);
    v.x *= s; v.y *= s; v.z *= s; v.w *= s;
    *(float4*)(out + e) = v;
}

// ---------------- launcher ----------------
extern "C" void kernel_launch(void* const* d_in, const int* in_sizes, int n_in,
                              void* d_out, int out_size)
{
    const float* x = (const float*)d_in[0];
    float* out = (float*)d_out;

    float *A, *mean, *itr, *str, *cs;
    cudaGetSymbolAddress((void**)&A,    g_A);
    cudaGetSymbolAddress((void**)&mean, g_mean);
    cudaGetSymbolAddress((void**)&itr,  g_itr);
    cudaGetSymbolAddress((void**)&str,  g_str);
    cudaGetSymbolAddress((void**)&cs,   g_cs);

    cudaFuncSetAttribute(cov_gemm, cudaFuncAttributeMaxDynamicSharedMemorySize, GEMM_SMEM);

    // 1) row means
    mean_kernel<<<(B_*C_ + 7) / 8, 256>>>(x, mean);

    // 2) covariance (symmetric: 10 upper-tri tiles, write both halves)
    cov_gemm<<<dim3(10, 1, B_), GT, GEMM_SMEM>>>(x, A, mean);

    // 3) trace scalars
    trace_kernel<<<B_, 512>>>(A, itr, str);

    // 4) Newton-Schulz chain: 122 matvecs, single CTA per batch, iterative driver
    chain_kernel<<<B_, 1024>>>(A, itr, str, cs);

    // 5) out = cov_sum[b][c] * x
    const long total4 = (long)B_ * C_ * M_ / 4;
    scale_kernel<<<(int)((total4 + 255) / 256), 256>>>(x, cs, out);

    (void)in_sizes; (void)n_in; (void)out_size;
}

// round 11
// speedup vs baseline: 3.0990x; 1.0170x over previous
#include <cuda_runtime.h>
#include <math.h>
#include <stdint.h>

// Problem constants
#define B_  32
#define C_  512
#define M_  784            // 28*28
#define NSQ (C_*C_)        // 262144

// ---------------- scratch ----------------
__device__ float g_A [B_*NSQ];   // covariance matrices
__device__ float g_mean[B_*C_];
__device__ float g_itr[B_];      // 1/trace
__device__ float g_str[B_];      // sqrt(trace)
__device__ float g_cs [B_*C_];   // final column means

// ================= warp-level tf32 MMA (sm_80 ISA) =================
__device__ __forceinline__ void mma_tf32(float* c, const uint32_t* a, const uint32_t* b) {
    asm volatile("mma.sync.aligned.m16n8k8.row.col.f32.tf32.tf32.f32 "
        "{%0,%1,%2,%3}, {%4,%5,%6,%7}, {%8,%9}, {%0,%1,%2,%3};"
        : "+f"(c[0]), "+f"(c[1]), "+f"(c[2]), "+f"(c[3])
        : "r"(a[0]), "r"(a[1]), "r"(a[2]), "r"(a[3]), "r"(b[0]), "r"(b[1]));
}
#define HI_MASK 0xFFFFE000u
__device__ __forceinline__ void split_tf32(float x, uint32_t& hi, uint32_t& lo) {
    uint32_t xb = __float_as_uint(x);
    hi = xb & HI_MASK;
    float lof = x - __uint_as_float(hi);
    lo = __float_as_uint(lof) & HI_MASK;
}

// ================= covariance GEMM (symmetric, upper-tri tiles only) =================
#define KCH  32
#define GT   256
#define APAD 36
#define ATILE_F (128*APAD)
#define STAGE_F (2*ATILE_F)
#define GEMM_SMEM (2*STAGE_F*4)   // 73728 bytes

__constant__ int c_bi[10] = {0,0,0,0,1,1,1,2,2,3};
__constant__ int c_bj[10] = {0,1,2,3,1,2,3,2,3,3};

__global__ void __launch_bounds__(GT)
cov_gemm(const float* __restrict__ xg, float* __restrict__ Cg,
         const float* __restrict__ meang)
{
    extern __shared__ float sm[];
    const int tid = threadIdx.x;
    const int b = blockIdx.z;
    const float* A  = xg + (long)b * C_ * M_;
    float*       C  = Cg + (long)b * NSQ;
    const int ib = c_bi[blockIdx.x] * 128;
    const int jb = c_bj[blockIdx.x] * 128;
    const int K = M_;
    const float covInvM = 1.0f / M_;

    const int wid = tid >> 5, lane = tid & 31;
    const int wm = wid & 1, wn = wid >> 1;
    const int gid = lane >> 2, tig = lane & 3;

    float acc[4][4][4];
    #pragma unroll
    for (int mf = 0; mf < 4; mf++)
        #pragma unroll
        for (int nf = 0; nf < 4; nf++)
            #pragma unroll
            for (int e = 0; e < 4; e++) acc[mf][nf][e] = 0.f;

    const int NC = (K + KCH - 1) / KCH;
    float4 ra[4], rb[4];

    #pragma unroll
    for (int q = 0; q < 4; q++) {
        int f = tid + q * GT; int r = f >> 3; int k = (f & 7) * 4;
        ra[q] = (k < K) ? *(const float4*)(A + (long)(ib + r) * M_ + k) : make_float4(0,0,0,0);
        rb[q] = (k < K) ? *(const float4*)(A + (long)(jb + r) * M_ + k) : make_float4(0,0,0,0);
    }
    #pragma unroll
    for (int q = 0; q < 4; q++) {
        int f = tid + q * GT; int r = f >> 3; int c = (f & 7) * 4;
        *(float4*)(sm + (long)r * APAD + c)           = ra[q];
        *(float4*)(sm + ATILE_F + (long)r * APAD + c) = rb[q];
    }
    __syncthreads();

    for (int i = 0; i < NC; i++) {
        if (i + 1 < NC) {
            const int k0 = (i + 1) * KCH;
            #pragma unroll
            for (int q = 0; q < 4; q++) {
                int f = tid + q * GT; int r = f >> 3; int k = k0 + (f & 7) * 4;
                ra[q] = (k < K) ? *(const float4*)(A + (long)(ib + r) * M_ + k) : make_float4(0,0,0,0);
                rb[q] = (k < K) ? *(const float4*)(A + (long)(jb + r) * M_ + k) : make_float4(0,0,0,0);
            }
        }
        const float* As = sm + (i & 1) * STAGE_F;
        const float* Bs = As + ATILE_F;
        #pragma unroll
        for (int ks = 0; ks < 4; ks++) {
            uint32_t ah[4][4], al[4][4];
            #pragma unroll
            for (int mf = 0; mf < 4; mf++) {
                int base = (wm * 64 + mf * 16 + gid) * APAD + ks * 8 + tig;
                split_tf32(As[base],                ah[mf][0], al[mf][0]);
                split_tf32(As[base + 8 * APAD],     ah[mf][1], al[mf][1]);
                split_tf32(As[base + 4],            ah[mf][2], al[mf][2]);
                split_tf32(As[base + 8 * APAD + 4], ah[mf][3], al[mf][3]);
            }
            uint32_t bh[4][2], bl[4][2];
            #pragma unroll
            for (int nf = 0; nf < 4; nf++) {
                int base = (wn * 32 + nf * 8 + gid) * APAD + ks * 8 + tig;
                split_tf32(Bs[base],     bh[nf][0], bl[nf][0]);
                split_tf32(Bs[base + 4], bh[nf][1], bl[nf][1]);
            }
            #pragma unroll
            for (int mf = 0; mf < 4; mf++)
                #pragma unroll
                for (int nf = 0; nf < 4; nf++) {
                    mma_tf32(acc[mf][nf], ah[mf], bh[nf]);
                    mma_tf32(acc[mf][nf], ah[mf], bl[nf]);
                    mma_tf32(acc[mf][nf], al[mf], bh[nf]);
                }
        }
        if (i + 1 < NC) {
            float* Ad = sm + ((i + 1) & 1) * STAGE_F;
            #pragma unroll
            for (int q = 0; q < 4; q++) {
                int f = tid + q * GT; int r = f >> 3; int c = (f & 7) * 4;
                *(float4*)(Ad + (long)r * APAD + c)           = ra[q];
                *(float4*)(Ad + ATILE_F + (long)r * APAD + c) = rb[q];
            }
        }
        __syncthreads();
    }

    const bool offdiag = (ib != jb);
    #pragma unroll
    for (int mf = 0; mf < 4; mf++) {
        const int row0 = ib + wm * 64 + mf * 16 + gid;
        float mi0 = meang[b * C_ + row0];
        float mi1 = meang[b * C_ + row0 + 8];
        #pragma unroll
        for (int nf = 0; nf < 4; nf++) {
            const int col0 = jb + wn * 32 + nf * 8 + tig * 2;
            float mj0 = meang[b * C_ + col0], mj1 = meang[b * C_ + col0 + 1];
            float c0 = acc[mf][nf][0] * covInvM - mi0 * mj0;
            float c1 = acc[mf][nf][1] * covInvM - mi0 * mj1;
            float c2 = acc[mf][nf][2] * covInvM - mi1 * mj0;
            float c3 = acc[mf][nf][3] * covInvM - mi1 * mj1;
            *(float2*)(C + (long)row0 * C_ + col0)       = make_float2(c0, c1);
            *(float2*)(C + (long)(row0 + 8) * C_ + col0) = make_float2(c2, c3);
            if (offdiag) {
                C[(long)col0 * C_ + row0]           = c0;
                C[(long)(col0 + 1) * C_ + row0]     = c1;
                C[(long)col0 * C_ + row0 + 8]       = c2;
                C[(long)(col0 + 1) * C_ + row0 + 8] = c3;
            }
        }
    }
}

// ---------------- per-row mean of x ----------------
__global__ void mean_kernel(const float* __restrict__ x, float* __restrict__ mean)
{
    int warp = (blockIdx.x * blockDim.x + threadIdx.x) >> 5;
    int lane = threadIdx.x & 31;
    if (warp >= B_*C_) return;
    const float* row = x + (long)warp * M_;
    float s = 0.f;
    for (int k = lane; k < M_; k += 32) s += row[k];
    #pragma unroll
    for (int off = 16; off; off >>= 1) s += __shfl_down_sync(0xffffffffu, s, off);
    if (lane == 0) mean[warp] = s * (1.0f / M_);
}

// ---------------- trace ----------------
__global__ void trace_kernel(const float* __restrict__ A,
                             float* __restrict__ itr, float* __restrict__ str)
{
    __shared__ float sh[512];
    const int b = blockIdx.x;
    const int i = threadIdx.x;
    sh[i] = A[(long)b * NSQ + (long)i * C_ + i];
    __syncthreads();
    for (int off = 256; off; off >>= 1) {
        if (i < off) sh[i] += sh[i + off];
        __syncthreads();
    }
    if (i == 0) { float t = sh[0]; itr[b] = 1.0f / t; str[b] = sqrtf(t); }
}

// ================= Newton-Schulz vector chain (single CTA, 512 threads) =================
// Ysqrt/sqrt(tr) = T * W0..W4, W_k = 1.5I - 0.5 S_k, S_0 = T, S_{k+1} = S_k W_k^2.
// 122 sequential matvecs via explicit state machine. Thread t owns output column t
// across ALL 512 rows: one 128B line per warp-row-load, v via LDS.128 broadcast,
// NO cross-thread reduction. 512 threads -> 128-reg budget -> deep load pipelining.
struct ChainCtx {
    const float* Ab;
    float* v;          // smem current vector [512]
    float* pool;       // smem save stack [5*512]
    float  inv;
    int    tid;
};

__device__ void do_matvec(ChainCtx& c)
{
    const int col = c.tid;                 // 0..511
    const float* base = c.Ab + col;
    const float* vs = c.v;

    float acc0 = 0.f, acc1 = 0.f, acc2 = 0.f, acc3 = 0.f;
    #pragma unroll
    for (int i = 0; i < 512; i += 16) {
        float t[16];
        #pragma unroll
        for (int r = 0; r < 16; r++)
            t[r] = base[(long)(i + r) * C_];
        float4 v0 = *(const float4*)(vs + i);
        float4 v1 = *(const float4*)(vs + i + 4);
        float4 v2 = *(const float4*)(vs + i + 8);
        float4 v3 = *(const float4*)(vs + i + 12);
        acc0 = fmaf(v0.x, t[0],  acc0);
        acc1 = fmaf(v0.y, t[1],  acc1);
        acc2 = fmaf(v0.z, t[2],  acc2);
        acc3 = fmaf(v0.w, t[3],  acc3);
        acc0 = fmaf(v1.x, t[4],  acc0);
        acc1 = fmaf(v1.y, t[5],  acc1);
        acc2 = fmaf(v1.z, t[6],  acc2);
        acc3 = fmaf(v1.w, t[7],  acc3);
        acc0 = fmaf(v2.x, t[8],  acc0);
        acc1 = fmaf(v2.y, t[9],  acc1);
        acc2 = fmaf(v2.z, t[10], acc2);
        acc3 = fmaf(v2.w, t[11], acc3);
        acc0 = fmaf(v3.x, t[12], acc0);
        acc1 = fmaf(v3.y, t[13], acc1);
        acc2 = fmaf(v3.z, t[14], acc2);
        acc3 = fmaf(v3.w, t[15], acc3);
    }
    const float r = ((acc0 + acc1) + (acc2 + acc3)) * c.inv;
    __syncthreads();          // everyone done READING v
    c.v[col] = r;
    __syncthreads();          // new v visible
}

// Iterative execution of applyW(k0, sp=0):
//   W(k,sp): save(sp); S(k, sp+1); v = 1.5*save - 0.5*v
//   S(k,sp): k==0 ? matvec : { S(k-1,sp); W(k-1,sp); W(k-1,sp); }
__device__ void exec_W(int k0, ChainCtx& c)
{
    int ty[16], kk[16], sp[16], st[16];
    int top = 0;
    ty[0] = 0; kk[0] = k0; sp[0] = 0; st[0] = 0; top = 1;
    while (top > 0) {
        const int i = top - 1;
        if (ty[i] == 0) {                       // W frame
            if (st[i] == 0) {
                float* save = c.pool + sp[i] * 512;
                save[c.tid] = c.v[c.tid];
                __syncthreads();
                st[i] = 1;
                ty[top] = 1; kk[top] = kk[i]; sp[top] = sp[i] + 1; st[top] = 0; top++;
            } else {
                float* save = c.pool + sp[i] * 512;
                float nv = 1.5f * save[c.tid] - 0.5f * c.v[c.tid];
                __syncthreads();
                c.v[c.tid] = nv;
                __syncthreads();
                top--;
            }
        } else {                                // S frame
            if (kk[i] == 0) { do_matvec(c); top--; }
            else if (st[i] == 0) {
                st[i] = 1;
                ty[top] = 1; kk[top] = kk[i] - 1; sp[top] = sp[i]; st[top] = 0; top++;
            } else if (st[i] == 1) {
                st[i] = 2;
                ty[top] = 0; kk[top] = kk[i] - 1; sp[top] = sp[i]; st[top] = 0; top++;
            } else if (st[i] == 2) {
                st[i] = 3;
                ty[top] = 0; kk[top] = kk[i] - 1; sp[top] = sp[i]; st[top] = 0; top++;
            } else top--;
        }
    }
}

__global__ void __launch_bounds__(512, 1)
chain_kernel(const float* __restrict__ A, const float* __restrict__ itr,
             const float* __restrict__ str, float* __restrict__ cs)
{
    __shared__ float v[512];
    __shared__ float pool[5 * 512];
    const int b = blockIdx.x;
    const int tid = threadIdx.x;

    ChainCtx c;
    c.Ab = A + (long)b * NSQ;
    c.v = v; c.pool = pool;
    c.inv = itr[b]; c.tid = tid;

    v[tid] = 1.0f;
    __syncthreads();

    do_matvec(c);                 // u = 1^T * T
    for (int k = 0; k < 5; k++)   // u = u * W_k
        exec_W(k, c);

    cs[b * C_ + tid] = v[tid] * str[b] * (1.0f / C_);
}

// ---------------- out = cov_sum * x ----------------
__global__ void scale_kernel(const float* __restrict__ x,
                             const float* __restrict__ cs, float* __restrict__ out)
{
    long i4 = (long)blockIdx.x * blockDim.x + threadIdx.x;
    const long total4 = (long)B_ * C_ * M_ / 4;
    if (i4 >= total4) return;
    long e = i4 * 4;
    int bc = (int)(e / M_);
    float s = cs[bc];
    float4 v = *(const float4*)(x + e);
    v.x *= s; v.y *= s; v.z *= s; v.w *= s;
    *(float4*)(out + e) = v;
}

// ---------------- launcher ----------------
extern "C" void kernel_launch(void* const* d_in, const int* in_sizes, int n_in,
                              void* d_out, int out_size)
{
    const float* x = (const float*)d_in[0];
    float* out = (float*)d_out;

    float *A, *mean, *itr, *str, *cs;
    cudaGetSymbolAddress((void**)&A,    g_A);
    cudaGetSymbolAddress((void**)&mean, g_mean);
    cudaGetSymbolAddress((void**)&itr,  g_itr);
    cudaGetSymbolAddress((void**)&str,  g_str);
    cudaGetSymbolAddress((void**)&cs,   g_cs);

    cudaFuncSetAttribute(cov_gemm, cudaFuncAttributeMaxDynamicSharedMemorySize, GEMM_SMEM);

    // 1) row means
    mean_kernel<<<(B_*C_ + 7) / 8, 256>>>(x, mean);

    // 2) covariance (symmetric: 10 upper-tri tiles, write both halves)
    cov_gemm<<<dim3(10, 1, B_), GT, GEMM_SMEM>>>(x, A, mean);

    // 3) trace scalars
    trace_kernel<<<B_, 512>>>(A, itr, str);

    // 4) Newton-Schulz chain: 122 matvecs, single CTA per batch, column-owner threads
    chain_kernel<<<B_, 512>>>(A, itr, str, cs);

    // 5) out = cov_sum[b][c] * x
    const long total4 = (long)B_ * C_ * M_ / 4;
    scale_kernel<<<(int)((total4 + 255) / 256), 256>>>(x, cs, out);

    (void)in_sizes; (void)n_in; (void)out_size;
}

// round 12
// speedup vs baseline: 3.2273x; 1.0414x over previous
#include <cuda_runtime.h>
#include <cuda_fp16.h>
#include <math.h>
#include <stdint.h>

// Problem constants
#define B_  32
#define C_  512
#define M_  784            // 28*28
#define NSQ (C_*C_)        // 262144
#define TOT ((long)B_*NSQ)

// ---------------- scratch ----------------
__device__ float  g_A [B_*NSQ];   // covariance matrices (fp32)
__device__ __half g_Ah[B_*NSQ];   // covariance in fp16 for the matvec chain
__device__ float  g_mean[B_*C_];
__device__ float  g_itr[B_];      // 1/trace
__device__ float  g_str[B_];      // sqrt(trace)
__device__ float  g_cs [B_*C_];   // final column means

// ================= warp-level tf32 MMA (sm_80 ISA) =================
__device__ __forceinline__ void mma_tf32(float* c, const uint32_t* a, const uint32_t* b) {
    asm volatile("mma.sync.aligned.m16n8k8.row.col.f32.tf32.tf32.f32 "
        "{%0,%1,%2,%3}, {%4,%5,%6,%7}, {%8,%9}, {%0,%1,%2,%3};"
        : "+f"(c[0]), "+f"(c[1]), "+f"(c[2]), "+f"(c[3])
        : "r"(a[0]), "r"(a[1]), "r"(a[2]), "r"(a[3]), "r"(b[0]), "r"(b[1]));
}
#define HI_MASK 0xFFFFE000u
__device__ __forceinline__ void split_tf32(float x, uint32_t& hi, uint32_t& lo) {
    uint32_t xb = __float_as_uint(x);
    hi = xb & HI_MASK;
    float lof = x - __uint_as_float(hi);
    lo = __float_as_uint(lof) & HI_MASK;
}

// ================= covariance GEMM (symmetric, upper-tri tiles only) =================
#define KCH  32
#define GT   256
#define APAD 36
#define ATILE_F (128*APAD)
#define STAGE_F (2*ATILE_F)
#define GEMM_SMEM (2*STAGE_F*4)   // 73728 bytes

__constant__ int c_bi[10] = {0,0,0,0,1,1,1,2,2,3};
__constant__ int c_bj[10] = {0,1,2,3,1,2,3,2,3,3};

__global__ void __launch_bounds__(GT)
cov_gemm(const float* __restrict__ xg, float* __restrict__ Cg,
         const float* __restrict__ meang)
{
    extern __shared__ float sm[];
    const int tid = threadIdx.x;
    const int b = blockIdx.z;
    const float* A  = xg + (long)b * C_ * M_;
    float*       C  = Cg + (long)b * NSQ;
    const int ib = c_bi[blockIdx.x] * 128;
    const int jb = c_bj[blockIdx.x] * 128;
    const int K = M_;
    const float covInvM = 1.0f / M_;

    const int wid = tid >> 5, lane = tid & 31;
    const int wm = wid & 1, wn = wid >> 1;
    const int gid = lane >> 2, tig = lane & 3;

    float acc[4][4][4];
    #pragma unroll
    for (int mf = 0; mf < 4; mf++)
        #pragma unroll
        for (int nf = 0; nf < 4; nf++)
            #pragma unroll
            for (int e = 0; e < 4; e++) acc[mf][nf][e] = 0.f;

    const int NC = (K + KCH - 1) / KCH;
    float4 ra[4], rb[4];

    #pragma unroll
    for (int q = 0; q < 4; q++) {
        int f = tid + q * GT; int r = f >> 3; int k = (f & 7) * 4;
        ra[q] = (k < K) ? *(const float4*)(A + (long)(ib + r) * M_ + k) : make_float4(0,0,0,0);
        rb[q] = (k < K) ? *(const float4*)(A + (long)(jb + r) * M_ + k) : make_float4(0,0,0,0);
    }
    #pragma unroll
    for (int q = 0; q < 4; q++) {
        int f = tid + q * GT; int r = f >> 3; int c = (f & 7) * 4;
        *(float4*)(sm + (long)r * APAD + c)           = ra[q];
        *(float4*)(sm + ATILE_F + (long)r * APAD + c) = rb[q];
    }
    __syncthreads();

    for (int i = 0; i < NC; i++) {
        if (i + 1 < NC) {
            const int k0 = (i + 1) * KCH;
            #pragma unroll
            for (int q = 0; q < 4; q++) {
                int f = tid + q * GT; int r = f >> 3; int k = k0 + (f & 7) * 4;
                ra[q] = (k < K) ? *(const float4*)(A + (long)(ib + r) * M_ + k) : make_float4(0,0,0,0);
                rb[q] = (k < K) ? *(const float4*)(A + (long)(jb + r) * M_ + k) : make_float4(0,0,0,0);
            }
        }
        const float* As = sm + (i & 1) * STAGE_F;
        const float* Bs = As + ATILE_F;
        #pragma unroll
        for (int ks = 0; ks < 4; ks++) {
            uint32_t ah[4][4], al[4][4];
            #pragma unroll
            for (int mf = 0; mf < 4; mf++) {
                int base = (wm * 64 + mf * 16 + gid) * APAD + ks * 8 + tig;
                split_tf32(As[base],                ah[mf][0], al[mf][0]);
                split_tf32(As[base + 8 * APAD],     ah[mf][1], al[mf][1]);
                split_tf32(As[base + 4],            ah[mf][2], al[mf][2]);
                split_tf32(As[base + 8 * APAD + 4], ah[mf][3], al[mf][3]);
            }
            uint32_t bh[4][2], bl[4][2];
            #pragma unroll
            for (int nf = 0; nf < 4; nf++) {
                int base = (wn * 32 + nf * 8 + gid) * APAD + ks * 8 + tig;
                split_tf32(Bs[base],     bh[nf][0], bl[nf][0]);
                split_tf32(Bs[base + 4], bh[nf][1], bl[nf][1]);
            }
            #pragma unroll
            for (int mf = 0; mf < 4; mf++)
                #pragma unroll
                for (int nf = 0; nf < 4; nf++) {
                    mma_tf32(acc[mf][nf], ah[mf], bh[nf]);
                    mma_tf32(acc[mf][nf], ah[mf], bl[nf]);
                    mma_tf32(acc[mf][nf], al[mf], bh[nf]);
                }
        }
        if (i + 1 < NC) {
            float* Ad = sm + ((i + 1) & 1) * STAGE_F;
            #pragma unroll
            for (int q = 0; q < 4; q++) {
                int f = tid + q * GT; int r = f >> 3; int c = (f & 7) * 4;
                *(float4*)(Ad + (long)r * APAD + c)           = ra[q];
                *(float4*)(Ad + ATILE_F + (long)r * APAD + c) = rb[q];
            }
        }
        __syncthreads();
    }

    const bool offdiag = (ib != jb);
    #pragma unroll
    for (int mf = 0; mf < 4; mf++) {
        const int row0 = ib + wm * 64 + mf * 16 + gid;
        float mi0 = meang[b * C_ + row0];
        float mi1 = meang[b * C_ + row0 + 8];
        #pragma unroll
        for (int nf = 0; nf < 4; nf++) {
            const int col0 = jb + wn * 32 + nf * 8 + tig * 2;
            float mj0 = meang[b * C_ + col0], mj1 = meang[b * C_ + col0 + 1];
            float c0 = acc[mf][nf][0] * covInvM - mi0 * mj0;
            float c1 = acc[mf][nf][1] * covInvM - mi0 * mj1;
            float c2 = acc[mf][nf][2] * covInvM - mi1 * mj0;
            float c3 = acc[mf][nf][3] * covInvM - mi1 * mj1;
            *(float2*)(C + (long)row0 * C_ + col0)       = make_float2(c0, c1);
            *(float2*)(C + (long)(row0 + 8) * C_ + col0) = make_float2(c2, c3);
            if (offdiag) {
                C[(long)col0 * C_ + row0]           = c0;
                C[(long)(col0 + 1) * C_ + row0]     = c1;
                C[(long)col0 * C_ + row0 + 8]       = c2;
                C[(long)(col0 + 1) * C_ + row0 + 8] = c3;
            }
        }
    }
}

// ---------------- fp32 -> fp16 conversion of covariance ----------------
__global__ void tohalf_kernel(const float* __restrict__ A, __half* __restrict__ Ah)
{
    long i = (long)blockIdx.x * blockDim.x + threadIdx.x;   // per 2 elements
    if (i >= TOT / 2) return;
    float2 f = *(const float2*)(A + i * 2);
    *(__half2*)(Ah + i * 2) = __floats2half2_rn(f.x, f.y);
}

// ---------------- per-row mean of x ----------------
__global__ void mean_kernel(const float* __restrict__ x, float* __restrict__ mean)
{
    int warp = (blockIdx.x * blockDim.x + threadIdx.x) >> 5;
    int lane = threadIdx.x & 31;
    if (warp >= B_*C_) return;
    const float* row = x + (long)warp * M_;
    float s = 0.f;
    for (int k = lane; k < M_; k += 32) s += row[k];
    #pragma unroll
    for (int off = 16; off; off >>= 1) s += __shfl_down_sync(0xffffffffu, s, off);
    if (lane == 0) mean[warp] = s * (1.0f / M_);
}

// ---------------- trace ----------------
__global__ void trace_kernel(const float* __restrict__ A,
                             float* __restrict__ itr, float* __restrict__ str)
{
    __shared__ float sh[512];
    const int b = blockIdx.x;
    const int i = threadIdx.x;
    sh[i] = A[(long)b * NSQ + (long)i * C_ + i];
    __syncthreads();
    for (int off = 256; off; off >>= 1) {
        if (i < off) sh[i] += sh[i + off];
        __syncthreads();
    }
    if (i == 0) { float t = sh[0]; itr[b] = 1.0f / t; str[b] = sqrtf(t); }
}

// ================= Newton-Schulz vector chain (single CTA, fp16 matrix) =================
// Ysqrt/sqrt(tr) = T * W0..W4, W_k = 1.5I - 0.5 S_k, S_0 = T, S_{k+1} = S_k W_k^2.
// 122 sequential matvecs via explicit state machine. Matrix in fp16: warp w reads
// 64 columns (one 128B half2 line) per row -> 4096 wavefronts & 512KB per step.
struct ChainCtx {
    const __half* Ah;
    float* v;          // smem current vector [512]
    float* partial;    // smem [2*512]
    float* pool;       // smem save stack [5*512]
    float  inv;
    int    tid;
};

__device__ void do_matvec(ChainCtx& c)
{
    const int w = c.tid >> 5, lane = c.tid & 31;
    const int g = w & 7;          // column group: cols [g*64, g*64+64)
    const int h = w >> 3;         // row half: rows [h*256, h*256+256)
    const __half2* base = (const __half2*)(c.Ah + (long)h * 256 * C_ + g * 64) + lane;
    const float* vs = c.v + h * 256;

    float ax0 = 0.f, ay0 = 0.f, ax1 = 0.f, ay1 = 0.f;
    #pragma unroll
    for (int i = 0; i < 256; i += 16) {
        __half2 t[16];
        #pragma unroll
        for (int r = 0; r < 16; r++)
            t[r] = base[(long)(i + r) * 256];   // row stride = 256 half2
        #pragma unroll
        for (int r = 0; r < 16; r += 2) {
            float2 f0 = __half22float2(t[r]);
            float2 f1 = __half22float2(t[r + 1]);
            float s0 = vs[i + r], s1 = vs[i + r + 1];
            ax0 = fmaf(s0, f0.x, ax0);
            ay0 = fmaf(s0, f0.y, ay0);
            ax1 = fmaf(s1, f1.x, ax1);
            ay1 = fmaf(s1, f1.y, ay1);
        }
    }
    c.partial[h * 512 + g * 64 + 2 * lane]     = ax0 + ax1;
    c.partial[h * 512 + g * 64 + 2 * lane + 1] = ay0 + ay1;
    __syncthreads();
    c.v[c.tid] = (c.partial[c.tid] + c.partial[512 + c.tid]) * c.inv;
    __syncthreads();
}

// Iterative execution of applyW(k0, sp=0):
//   W(k,sp): save(sp); S(k, sp+1); v = 1.5*save - 0.5*v
//   S(k,sp): k==0 ? matvec : { S(k-1,sp); W(k-1,sp); W(k-1,sp); }
__device__ void exec_W(int k0, ChainCtx& c)
{
    int ty[16], kk[16], sp[16], st[16];
    int top = 0;
    ty[0] = 0; kk[0] = k0; sp[0] = 0; st[0] = 0; top = 1;
    while (top > 0) {
        const int i = top - 1;
        if (ty[i] == 0) {                       // W frame
            if (st[i] == 0) {
                float* save = c.pool + sp[i] * 512;
                save[c.tid] = c.v[c.tid];
                __syncthreads();
                st[i] = 1;
                ty[top] = 1; kk[top] = kk[i]; sp[top] = sp[i] + 1; st[top] = 0; top++;
            } else {
                float* save = c.pool + sp[i] * 512;
                float nv = 1.5f * save[c.tid] - 0.5f * c.v[c.tid];
                __syncthreads();
                c.v[c.tid] = nv;
                __syncthreads();
                top--;
            }
        } else {                                // S frame
            if (kk[i] == 0) { do_matvec(c); top--; }
            else if (st[i] == 0) {
                st[i] = 1;
                ty[top] = 1; kk[top] = kk[i] - 1; sp[top] = sp[i]; st[top] = 0; top++;
            } else if (st[i] == 1) {
                st[i] = 2;
                ty[top] = 0; kk[top] = kk[i] - 1; sp[top] = sp[i]; st[top] = 0; top++;
            } else if (st[i] == 2) {
                st[i] = 3;
                ty[top] = 0; kk[top] = kk[i] - 1; sp[top] = sp[i]; st[top] = 0; top++;
            } else top--;
        }
    }
}

__global__ void __launch_bounds__(512, 1)
chain_kernel(const __half* __restrict__ Ah, const float* __restrict__ itr,
             const float* __restrict__ str, float* __restrict__ cs)
{
    __shared__ float v[512];
    __shared__ float partial[2 * 512];
    __shared__ float pool[5 * 512];
    const int b = blockIdx.x;
    const int tid = threadIdx.x;

    ChainCtx c;
    c.Ah = Ah + (long)b * NSQ;
    c.v = v; c.partial = partial; c.pool = pool;
    c.inv = itr[b]; c.tid = tid;

    v[tid] = 1.0f;
    __syncthreads();

    do_matvec(c);                 // u = 1^T * T
    for (int k = 0; k < 5; k++)   // u = u * W_k
        exec_W(k, c);

    cs[b * C_ + tid] = v[tid] * str[b] * (1.0f / C_);
}

// ---------------- out = cov_sum * x ----------------
__global__ void scale_kernel(const float* __restrict__ x,
                             const float* __restrict__ cs, float* __restrict__ out)
{
    long i4 = (long)blockIdx.x * blockDim.x + threadIdx.x;
    const long total4 = (long)B_ * C_ * M_ / 4;
    if (i4 >= total4) return;
    long e = i4 * 4;
    int bc = (int)(e / M_);
    float s = cs[bc];
    float4 v = *(const float4*)(x + e);
    v.x *= s; v.y *= s; v.z *= s; v.w *= s;
    *(float4*)(out + e) = v;
}

// ---------------- launcher ----------------
extern "C" void kernel_launch(void* const* d_in, const int* in_sizes, int n_in,
                              void* d_out, int out_size)
{
    const float* x = (const float*)d_in[0];
    float* out = (float*)d_out;

    float *A, *mean, *itr, *str, *cs;
    __half* Ah;
    cudaGetSymbolAddress((void**)&A,    g_A);
    cudaGetSymbolAddress((void**)&Ah,   g_Ah);
    cudaGetSymbolAddress((void**)&mean, g_mean);
    cudaGetSymbolAddress((void**)&itr,  g_itr);
    cudaGetSymbolAddress((void**)&str,  g_str);
    cudaGetSymbolAddress((void**)&cs,   g_cs);

    cudaFuncSetAttribute(cov_gemm, cudaFuncAttributeMaxDynamicSharedMemorySize, GEMM_SMEM);

    // 1) row means
    mean_kernel<<<(B_*C_ + 7) / 8, 256>>>(x, mean);

    // 2) covariance (symmetric: 10 upper-tri tiles, write both halves)
    cov_gemm<<<dim3(10, 1, B_), GT, GEMM_SMEM>>>(x, A, mean);

    // 3) trace scalars + fp16 conversion (independent, back-to-back)
    trace_kernel<<<B_, 512>>>(A, itr, str);
    tohalf_kernel<<<(int)((TOT / 2 + 255) / 256), 256>>>(A, Ah);

    // 4) Newton-Schulz chain: 122 matvecs on fp16 matrix, single CTA per batch
    chain_kernel<<<B_, 512>>>(Ah, itr, str, cs);

    // 5) out = cov_sum[b][c] * x
    const long total4 = (long)B_ * C_ * M_ / 4;
    scale_kernel<<<(int)((total4 + 255) / 256), 256>>>(x, cs, out);

    (void)in_sizes; (void)n_in; (void)out_size;
}

// round 13
// speedup vs baseline: 5.6626x; 1.7546x over previous
#include <cuda_runtime.h>
#include <cuda_fp16.h>
#include <math.h>
#include <stdint.h>

// Problem constants
#define B_  32
#define C_  512
#define M_  784            // 28*28
#define NSQ (C_*C_)        // 262144
#define TOT ((long)B_*NSQ)

// ---------------- scratch ----------------
__device__ float  g_A [B_*NSQ];   // covariance matrices (fp32)
__device__ __half g_Ah[B_*NSQ];   // covariance in fp16 for the matvec chain
__device__ float  g_mean[B_*C_];
__device__ float  g_itr[B_];      // 1/trace
__device__ float  g_str[B_];      // sqrt(trace)
__device__ float  g_cs [B_*C_];   // final column means

// ================= warp-level tf32 MMA (sm_80 ISA) =================
__device__ __forceinline__ void mma_tf32(float* c, const uint32_t* a, const uint32_t* b) {
    asm volatile("mma.sync.aligned.m16n8k8.row.col.f32.tf32.tf32.f32 "
        "{%0,%1,%2,%3}, {%4,%5,%6,%7}, {%8,%9}, {%0,%1,%2,%3};"
        : "+f"(c[0]), "+f"(c[1]), "+f"(c[2]), "+f"(c[3])
        : "r"(a[0]), "r"(a[1]), "r"(a[2]), "r"(a[3]), "r"(b[0]), "r"(b[1]));
}
#define HI_MASK 0xFFFFE000u
__device__ __forceinline__ void split_tf32(float x, uint32_t& hi, uint32_t& lo) {
    uint32_t xb = __float_as_uint(x);
    hi = xb & HI_MASK;
    float lof = x - __uint_as_float(hi);
    lo = __float_as_uint(lof) & HI_MASK;
}

// ================= covariance GEMM (symmetric, upper-tri tiles only) =================
#define KCH  32
#define GT   256
#define APAD 36
#define ATILE_F (128*APAD)
#define STAGE_F (2*ATILE_F)
#define GEMM_SMEM (2*STAGE_F*4)   // 73728 bytes

__constant__ int c_bi[10] = {0,0,0,0,1,1,1,2,2,3};
__constant__ int c_bj[10] = {0,1,2,3,1,2,3,2,3,3};

__global__ void __launch_bounds__(GT)
cov_gemm(const float* __restrict__ xg, float* __restrict__ Cg,
         const float* __restrict__ meang)
{
    extern __shared__ float sm[];
    const int tid = threadIdx.x;
    const int b = blockIdx.z;
    const float* A  = xg + (long)b * C_ * M_;
    float*       C  = Cg + (long)b * NSQ;
    const int ib = c_bi[blockIdx.x] * 128;
    const int jb = c_bj[blockIdx.x] * 128;
    const int K = M_;
    const float covInvM = 1.0f / M_;

    const int wid = tid >> 5, lane = tid & 31;
    const int wm = wid & 1, wn = wid >> 1;
    const int gid = lane >> 2, tig = lane & 3;

    float acc[4][4][4];
    #pragma unroll
    for (int mf = 0; mf < 4; mf++)
        #pragma unroll
        for (int nf = 0; nf < 4; nf++)
            #pragma unroll
            for (int e = 0; e < 4; e++) acc[mf][nf][e] = 0.f;

    const int NC = (K + KCH - 1) / KCH;
    float4 ra[4], rb[4];

    #pragma unroll
    for (int q = 0; q < 4; q++) {
        int f = tid + q * GT; int r = f >> 3; int k = (f & 7) * 4;
        ra[q] = (k < K) ? *(const float4*)(A + (long)(ib + r) * M_ + k) : make_float4(0,0,0,0);
        rb[q] = (k < K) ? *(const float4*)(A + (long)(jb + r) * M_ + k) : make_float4(0,0,0,0);
    }
    #pragma unroll
    for (int q = 0; q < 4; q++) {
        int f = tid + q * GT; int r = f >> 3; int c = (f & 7) * 4;
        *(float4*)(sm + (long)r * APAD + c)           = ra[q];
        *(float4*)(sm + ATILE_F + (long)r * APAD + c) = rb[q];
    }
    __syncthreads();

    for (int i = 0; i < NC; i++) {
        if (i + 1 < NC) {
            const int k0 = (i + 1) * KCH;
            #pragma unroll
            for (int q = 0; q < 4; q++) {
                int f = tid + q * GT; int r = f >> 3; int k = k0 + (f & 7) * 4;
                ra[q] = (k < K) ? *(const float4*)(A + (long)(ib + r) * M_ + k) : make_float4(0,0,0,0);
                rb[q] = (k < K) ? *(const float4*)(A + (long)(jb + r) * M_ + k) : make_float4(0,0,0,0);
            }
        }
        const float* As = sm + (i & 1) * STAGE_F;
        const float* Bs = As + ATILE_F;
        #pragma unroll
        for (int ks = 0; ks < 4; ks++) {
            uint32_t ah[4][4], al[4][4];
            #pragma unroll
            for (int mf = 0; mf < 4; mf++) {
                int base = (wm * 64 + mf * 16 + gid) * APAD + ks * 8 + tig;
                split_tf32(As[base],                ah[mf][0], al[mf][0]);
                split_tf32(As[base + 8 * APAD],     ah[mf][1], al[mf][1]);
                split_tf32(As[base + 4],            ah[mf][2], al[mf][2]);
                split_tf32(As[base + 8 * APAD + 4], ah[mf][3], al[mf][3]);
            }
            uint32_t bh[4][2], bl[4][2];
            #pragma unroll
            for (int nf = 0; nf < 4; nf++) {
                int base = (wn * 32 + nf * 8 + gid) * APAD + ks * 8 + tig;
                split_tf32(Bs[base],     bh[nf][0], bl[nf][0]);
                split_tf32(Bs[base + 4], bh[nf][1], bl[nf][1]);
            }
            #pragma unroll
            for (int mf = 0; mf < 4; mf++)
                #pragma unroll
                for (int nf = 0; nf < 4; nf++) {
                    mma_tf32(acc[mf][nf], ah[mf], bh[nf]);
                    mma_tf32(acc[mf][nf], ah[mf], bl[nf]);
                    mma_tf32(acc[mf][nf], al[mf], bh[nf]);
                }
        }
        if (i + 1 < NC) {
            float* Ad = sm + ((i + 1) & 1) * STAGE_F;
            #pragma unroll
            for (int q = 0; q < 4; q++) {
                int f = tid + q * GT; int r = f >> 3; int c = (f & 7) * 4;
                *(float4*)(Ad + (long)r * APAD + c)           = ra[q];
                *(float4*)(Ad + ATILE_F + (long)r * APAD + c) = rb[q];
            }
        }
        __syncthreads();
    }

    const bool offdiag = (ib != jb);
    #pragma unroll
    for (int mf = 0; mf < 4; mf++) {
        const int row0 = ib + wm * 64 + mf * 16 + gid;
        float mi0 = meang[b * C_ + row0];
        float mi1 = meang[b * C_ + row0 + 8];
        #pragma unroll
        for (int nf = 0; nf < 4; nf++) {
            const int col0 = jb + wn * 32 + nf * 8 + tig * 2;
            float mj0 = meang[b * C_ + col0], mj1 = meang[b * C_ + col0 + 1];
            float c0 = acc[mf][nf][0] * covInvM - mi0 * mj0;
            float c1 = acc[mf][nf][1] * covInvM - mi0 * mj1;
            float c2 = acc[mf][nf][2] * covInvM - mi1 * mj0;
            float c3 = acc[mf][nf][3] * covInvM - mi1 * mj1;
            *(float2*)(C + (long)row0 * C_ + col0)       = make_float2(c0, c1);
            *(float2*)(C + (long)(row0 + 8) * C_ + col0) = make_float2(c2, c3);
            if (offdiag) {
                C[(long)col0 * C_ + row0]           = c0;
                C[(long)(col0 + 1) * C_ + row0]     = c1;
                C[(long)col0 * C_ + row0 + 8]       = c2;
                C[(long)(col0 + 1) * C_ + row0 + 8] = c3;
            }
        }
    }
}

// ---------------- fp32 -> fp16 conversion of covariance ----------------
__global__ void tohalf_kernel(const float* __restrict__ A, __half* __restrict__ Ah)
{
    long i = (long)blockIdx.x * blockDim.x + threadIdx.x;   // per 2 elements
    if (i >= TOT / 2) return;
    float2 f = *(const float2*)(A + i * 2);
    *(__half2*)(Ah + i * 2) = __floats2half2_rn(f.x, f.y);
}

// ---------------- per-row mean of x ----------------
__global__ void mean_kernel(const float* __restrict__ x, float* __restrict__ mean)
{
    int warp = (blockIdx.x * blockDim.x + threadIdx.x) >> 5;
    int lane = threadIdx.x & 31;
    if (warp >= B_*C_) return;
    const float* row = x + (long)warp * M_;
    float s = 0.f;
    for (int k = lane; k < M_; k += 32) s += row[k];
    #pragma unroll
    for (int off = 16; off; off >>= 1) s += __shfl_down_sync(0xffffffffu, s, off);
    if (lane == 0) mean[warp] = s * (1.0f / M_);
}

// ---------------- trace ----------------
__global__ void trace_kernel(const float* __restrict__ A,
                             float* __restrict__ itr, float* __restrict__ str)
{
    __shared__ float sh[512];
    const int b = blockIdx.x;
    const int i = threadIdx.x;
    sh[i] = A[(long)b * NSQ + (long)i * C_ + i];
    __syncthreads();
    for (int off = 256; off; off >>= 1) {
        if (i < off) sh[i] += sh[i + off];
        __syncthreads();
    }
    if (i == 0) { float t = sh[0]; itr[b] = 1.0f / t; str[b] = sqrtf(t); }
}

// ================= Newton-Schulz vector chain (single CTA, fp16, LDG.128) =================
// Ysqrt/sqrt(tr) = T * W0..W4, W_k = 1.5I - 0.5 S_k, S_0 = T, S_{k+1} = S_k W_k^2.
// 122 sequential matvecs. Thread t owns 8 columns x 64 rows: one LDG.128 (8 halfs)
// + 1 broadcast LDS + 8 CVT + 8 FMA per row -> ~19 instr / 16B (issue-optimal).
struct ChainCtx {
    const __half* Ah;
    float* v;          // smem current vector [512]
    float* partial;    // smem [8*512]
    float* pool;       // smem save stack [5*512]
    float  inv;
    int    tid;
};

__device__ void do_matvec(ChainCtx& c)
{
    const int cg = c.tid & 63;        // column group: cols [cg*8, cg*8+8)
    const int rg = c.tid >> 6;        // row group: rows [rg*64, rg*64+64)
    const __half* base = c.Ah + (long)rg * 64 * C_ + cg * 8;
    const float* vs = c.v + rg * 64;

    float a0 = 0.f, a1 = 0.f, a2 = 0.f, a3 = 0.f;
    float a4 = 0.f, a5 = 0.f, a6 = 0.f, a7 = 0.f;
    #pragma unroll 8
    for (int r = 0; r < 64; r++) {
        uint4 q = *(const uint4*)(base + (long)r * C_);
        float s = vs[r];
        float2 f0 = __half22float2(*(__half2*)&q.x);
        float2 f1 = __half22float2(*(__half2*)&q.y);
        float2 f2 = __half22float2(*(__half2*)&q.z);
        float2 f3 = __half22float2(*(__half2*)&q.w);
        a0 = fmaf(s, f0.x, a0);
        a1 = fmaf(s, f0.y, a1);
        a2 = fmaf(s, f1.x, a2);
        a3 = fmaf(s, f1.y, a3);
        a4 = fmaf(s, f2.x, a4);
        a5 = fmaf(s, f2.y, a5);
        a6 = fmaf(s, f3.x, a6);
        a7 = fmaf(s, f3.y, a7);
    }
    *(float4*)(c.partial + rg * 512 + cg * 8)     = make_float4(a0, a1, a2, a3);
    *(float4*)(c.partial + rg * 512 + cg * 8 + 4) = make_float4(a4, a5, a6, a7);
    __syncthreads();                       // all v reads + partial writes done
    float sum = 0.f;
    #pragma unroll
    for (int g = 0; g < 8; g++) sum += c.partial[g * 512 + c.tid];
    c.v[c.tid] = sum * c.inv;
    __syncthreads();                       // new v visible
}

// Iterative execution of applyW(k0, sp=0):
//   W(k,sp): save(sp); S(k, sp+1); v = 1.5*save - 0.5*v
//   S(k,sp): k==0 ? matvec : { S(k-1,sp); W(k-1,sp); W(k-1,sp); }
__device__ void exec_W(int k0, ChainCtx& c)
{
    int ty[16], kk[16], sp[16], st[16];
    int top = 0;
    ty[0] = 0; kk[0] = k0; sp[0] = 0; st[0] = 0; top = 1;
    while (top > 0) {
        const int i = top - 1;
        if (ty[i] == 0) {                       // W frame
            if (st[i] == 0) {
                float* save = c.pool + sp[i] * 512;
                save[c.tid] = c.v[c.tid];
                __syncthreads();
                st[i] = 1;
                ty[top] = 1; kk[top] = kk[i]; sp[top] = sp[i] + 1; st[top] = 0; top++;
            } else {
                float* save = c.pool + sp[i] * 512;
                float nv = 1.5f * save[c.tid] - 0.5f * c.v[c.tid];
                __syncthreads();
                c.v[c.tid] = nv;
                __syncthreads();
                top--;
            }
        } else {                                // S frame
            if (kk[i] == 0) { do_matvec(c); top--; }
            else if (st[i] == 0) {
                st[i] = 1;
                ty[top] = 1; kk[top] = kk[i] - 1; sp[top] = sp[i]; st[top] = 0; top++;
            } else if (st[i] == 1) {
                st[i] = 2;
                ty[top] = 0; kk[top] = kk[i] - 1; sp[top] = sp[i]; st[top] = 0; top++;
            } else if (st[i] == 2) {
                st[i] = 3;
                ty[top] = 0; kk[top] = kk[i] - 1; sp[top] = sp[i]; st[top] = 0; top++;
            } else top--;
        }
    }
}

__global__ void __launch_bounds__(512, 1)
chain_kernel(const __half* __restrict__ Ah, const float* __restrict__ itr,
             const float* __restrict__ str, float* __restrict__ cs)
{
    __shared__ float v[512];
    __shared__ float partial[8 * 512];
    __shared__ float pool[5 * 512];
    const int b = blockIdx.x;
    const int tid = threadIdx.x;

    ChainCtx c;
    c.Ah = Ah + (long)b * NSQ;
    c.v = v; c.partial = partial; c.pool = pool;
    c.inv = itr[b]; c.tid = tid;

    v[tid] = 1.0f;
    __syncthreads();

    do_matvec(c);                 // u = 1^T * T
    for (int k = 0; k < 5; k++)   // u = u * W_k
        exec_W(k, c);

    cs[b * C_ + tid] = v[tid] * str[b] * (1.0f / C_);
}

// ---------------- out = cov_sum * x ----------------
__global__ void scale_kernel(const float* __restrict__ x,
                             const float* __restrict__ cs, float* __restrict__ out)
{
    long i4 = (long)blockIdx.x * blockDim.x + threadIdx.x;
    const long total4 = (long)B_ * C_ * M_ / 4;
    if (i4 >= total4) return;
    long e = i4 * 4;
    int bc = (int)(e / M_);
    float s = cs[bc];
    float4 v = *(const float4*)(x + e);
    v.x *= s; v.y *= s; v.z *= s; v.w *= s;
    *(float4*)(out + e) = v;
}

// ---------------- launcher ----------------
extern "C" void kernel_launch(void* const* d_in, const int* in_sizes, int n_in,
                              void* d_out, int out_size)
{
    const float* x = (const float*)d_in[0];
    float* out = (float*)d_out;

    float *A, *mean, *itr, *str, *cs;
    __half* Ah;
    cudaGetSymbolAddress((void**)&A,    g_A);
    cudaGetSymbolAddress((void**)&Ah,   g_Ah);
    cudaGetSymbolAddress((void**)&mean, g_mean);
    cudaGetSymbolAddress((void**)&itr,  g_itr);
    cudaGetSymbolAddress((void**)&str,  g_str);
    cudaGetSymbolAddress((void**)&cs,   g_cs);

    cudaFuncSetAttribute(cov_gemm, cudaFuncAttributeMaxDynamicSharedMemorySize, GEMM_SMEM);

    // 1) row means
    mean_kernel<<<(B_*C_ + 7) / 8, 256>>>(x, mean);

    // 2) covariance (symmetric: 10 upper-tri tiles, write both halves)
    cov_gemm<<<dim3(10, 1, B_), GT, GEMM_SMEM>>>(x, A, mean);

    // 3) trace scalars + fp16 conversion
    trace_kernel<<<B_, 512>>>(A, itr, str);
    tohalf_kernel<<<(int)((TOT / 2 + 255) / 256), 256>>>(A, Ah);

    // 4) Newton-Schulz chain: 122 matvecs on fp16 matrix, single CTA per batch
    chain_kernel<<<B_, 512>>>(Ah, itr, str, cs);

    // 5) out = cov_sum[b][c] * x
    const long total4 = (long)B_ * C_ * M_ / 4;
    scale_kernel<<<(int)((total4 + 255) / 256), 256>>>(x, cs, out);

    (void)in_sizes; (void)n_in; (void)out_size;
}

// round 14
// speedup vs baseline: 8.9815x; 1.5861x over previous
#include <cuda_runtime.h>
#include <cuda_fp16.h>
#include <math.h>
#include <stdint.h>

// Problem constants
#define B_  32
#define C_  512
#define M_  784            // 28*28
#define NSQ (C_*C_)        // 262144
#define TOT ((long)B_*NSQ)

// ---------------- scratch ----------------
__device__ float  g_A  [B_*NSQ];  // covariance matrices (fp32)
__device__ __half g_Th [B_*NSQ];  // T = cov/trace in fp16
__device__ __half g_T2h[B_*NSQ];  // T^2 in fp16
__device__ __half g_S1h[B_*NSQ];  // S1 = 2.25T - 1.5T^2 + 0.25T^3 in fp16
__device__ float  g_mean[B_*C_];
__device__ float  g_itr[B_];      // 1/trace
__device__ float  g_str[B_];      // sqrt(trace)
__device__ float  g_cs [B_*C_];   // final column means

// ================= warp-level MMA =================
__device__ __forceinline__ void mma_tf32(float* c, const uint32_t* a, const uint32_t* b) {
    asm volatile("mma.sync.aligned.m16n8k8.row.col.f32.tf32.tf32.f32 "
        "{%0,%1,%2,%3}, {%4,%5,%6,%7}, {%8,%9}, {%0,%1,%2,%3};"
        : "+f"(c[0]), "+f"(c[1]), "+f"(c[2]), "+f"(c[3])
        : "r"(a[0]), "r"(a[1]), "r"(a[2]), "r"(a[3]), "r"(b[0]), "r"(b[1]));
}
__device__ __forceinline__ void mma_f16(float* c, const uint32_t* a, const uint32_t* b) {
    asm volatile("mma.sync.aligned.m16n8k16.row.col.f32.f16.f16.f32 "
        "{%0,%1,%2,%3}, {%4,%5,%6,%7}, {%8,%9}, {%0,%1,%2,%3};"
        : "+f"(c[0]), "+f"(c[1]), "+f"(c[2]), "+f"(c[3])
        : "r"(a[0]), "r"(a[1]), "r"(a[2]), "r"(a[3]), "r"(b[0]), "r"(b[1]));
}
#define HI_MASK 0xFFFFE000u
__device__ __forceinline__ void split_tf32(float x, uint32_t& hi, uint32_t& lo) {
    uint32_t xb = __float_as_uint(x);
    hi = xb & HI_MASK;
    float lof = x - __uint_as_float(hi);
    lo = __float_as_uint(lof) & HI_MASK;
}

// ================= covariance GEMM (fp32, 3xTF32, upper-tri tiles) =================
#define KCH  32
#define GT   256
#define APAD 36
#define ATILE_F (128*APAD)
#define STAGE_F (2*ATILE_F)
#define GEMM_SMEM (2*STAGE_F*4)   // 73728 bytes

__constant__ int c_bi[10] = {0,0,0,0,1,1,1,2,2,3};
__constant__ int c_bj[10] = {0,1,2,3,1,2,3,2,3,3};

__global__ void __launch_bounds__(GT)
cov_gemm(const float* __restrict__ xg, float* __restrict__ Cg,
         const float* __restrict__ meang)
{
    extern __shared__ float sm[];
    const int tid = threadIdx.x;
    const int b = blockIdx.z;
    const float* A  = xg + (long)b * C_ * M_;
    float*       C  = Cg + (long)b * NSQ;
    const int ib = c_bi[blockIdx.x] * 128;
    const int jb = c_bj[blockIdx.x] * 128;
    const int K = M_;
    const float covInvM = 1.0f / M_;

    const int wid = tid >> 5, lane = tid & 31;
    const int wm = wid & 1, wn = wid >> 1;
    const int gid = lane >> 2, tig = lane & 3;

    float acc[4][4][4];
    #pragma unroll
    for (int mf = 0; mf < 4; mf++)
        #pragma unroll
        for (int nf = 0; nf < 4; nf++)
            #pragma unroll
            for (int e = 0; e < 4; e++) acc[mf][nf][e] = 0.f;

    const int NC = (K + KCH - 1) / KCH;
    float4 ra[4], rb[4];

    #pragma unroll
    for (int q = 0; q < 4; q++) {
        int f = tid + q * GT; int r = f >> 3; int k = (f & 7) * 4;
        ra[q] = (k < K) ? *(const float4*)(A + (long)(ib + r) * M_ + k) : make_float4(0,0,0,0);
        rb[q] = (k < K) ? *(const float4*)(A + (long)(jb + r) * M_ + k) : make_float4(0,0,0,0);
    }
    #pragma unroll
    for (int q = 0; q < 4; q++) {
        int f = tid + q * GT; int r = f >> 3; int c = (f & 7) * 4;
        *(float4*)(sm + (long)r * APAD + c)           = ra[q];
        *(float4*)(sm + ATILE_F + (long)r * APAD + c) = rb[q];
    }
    __syncthreads();

    for (int i = 0; i < NC; i++) {
        if (i + 1 < NC) {
            const int k0 = (i + 1) * KCH;
            #pragma unroll
            for (int q = 0; q < 4; q++) {
                int f = tid + q * GT; int r = f >> 3; int k = k0 + (f & 7) * 4;
                ra[q] = (k < K) ? *(const float4*)(A + (long)(ib + r) * M_ + k) : make_float4(0,0,0,0);
                rb[q] = (k < K) ? *(const float4*)(A + (long)(jb + r) * M_ + k) : make_float4(0,0,0,0);
            }
        }
        const float* As = sm + (i & 1) * STAGE_F;
        const float* Bs = As + ATILE_F;
        #pragma unroll
        for (int ks = 0; ks < 4; ks++) {
            uint32_t ah[4][4], al[4][4];
            #pragma unroll
            for (int mf = 0; mf < 4; mf++) {
                int base = (wm * 64 + mf * 16 + gid) * APAD + ks * 8 + tig;
                split_tf32(As[base],                ah[mf][0], al[mf][0]);
                split_tf32(As[base + 8 * APAD],     ah[mf][1], al[mf][1]);
                split_tf32(As[base + 4],            ah[mf][2], al[mf][2]);
                split_tf32(As[base + 8 * APAD + 4], ah[mf][3], al[mf][3]);
            }
            uint32_t bh[4][2], bl[4][2];
            #pragma unroll
            for (int nf = 0; nf < 4; nf++) {
                int base = (wn * 32 + nf * 8 + gid) * APAD + ks * 8 + tig;
                split_tf32(Bs[base],     bh[nf][0], bl[nf][0]);
                split_tf32(Bs[base + 4], bh[nf][1], bl[nf][1]);
            }
            #pragma unroll
            for (int mf = 0; mf < 4; mf++)
                #pragma unroll
                for (int nf = 0; nf < 4; nf++) {
                    mma_tf32(acc[mf][nf], ah[mf], bh[nf]);
                    mma_tf32(acc[mf][nf], ah[mf], bl[nf]);
                    mma_tf32(acc[mf][nf], al[mf], bh[nf]);
                }
        }
        if (i + 1 < NC) {
            float* Ad = sm + ((i + 1) & 1) * STAGE_F;
            #pragma unroll
            for (int q = 0; q < 4; q++) {
                int f = tid + q * GT; int r = f >> 3; int c = (f & 7) * 4;
                *(float4*)(Ad + (long)r * APAD + c)           = ra[q];
                *(float4*)(Ad + ATILE_F + (long)r * APAD + c) = rb[q];
            }
        }
        __syncthreads();
    }

    const bool offdiag = (ib != jb);
    #pragma unroll
    for (int mf = 0; mf < 4; mf++) {
        const int row0 = ib + wm * 64 + mf * 16 + gid;
        float mi0 = meang[b * C_ + row0];
        float mi1 = meang[b * C_ + row0 + 8];
        #pragma unroll
        for (int nf = 0; nf < 4; nf++) {
            const int col0 = jb + wn * 32 + nf * 8 + tig * 2;
            float mj0 = meang[b * C_ + col0], mj1 = meang[b * C_ + col0 + 1];
            float c0 = acc[mf][nf][0] * covInvM - mi0 * mj0;
            float c1 = acc[mf][nf][1] * covInvM - mi0 * mj1;
            float c2 = acc[mf][nf][2] * covInvM - mi1 * mj0;
            float c3 = acc[mf][nf][3] * covInvM - mi1 * mj1;
            *(float2*)(C + (long)row0 * C_ + col0)       = make_float2(c0, c1);
            *(float2*)(C + (long)(row0 + 8) * C_ + col0) = make_float2(c2, c3);
            if (offdiag) {
                C[(long)col0 * C_ + row0]           = c0;
                C[(long)(col0 + 1) * C_ + row0]     = c1;
                C[(long)col0 * C_ + row0 + 8]       = c2;
                C[(long)(col0 + 1) * C_ + row0 + 8] = c3;
            }
        }
    }
}

// ================= fp16 power GEMM: D = P * Q^T (both K-major, symmetric use) ===========
// MODE 0: D = fp16(acc)                      (T^2 = T*T)
// MODE 1: D = fp16(2.25*T1 - 1.5*T2 + 0.25*acc)   (S1 from T^3 = T2*T)
#define PPAD 40
#define PT_H (128*PPAD)
#define PSTG (2*PT_H)
#define POW_SMEM (2*PSTG*2)       // 40960 bytes

template<int MODE>
__global__ void __launch_bounds__(256)
pow_gemm(const __half* __restrict__ Pg, const __half* __restrict__ Qg,
         __half* __restrict__ Dg,
         const __half* __restrict__ T1g, const __half* __restrict__ T2g)
{
    extern __shared__ __half smh[];
    const int tid = threadIdx.x;
    const int b = blockIdx.z;
    const __half* P = Pg + (long)b * NSQ;
    const __half* Q = Qg + (long)b * NSQ;
    const int ib = blockIdx.y * 128, jb = blockIdx.x * 128;

    const int wid = tid >> 5, lane = tid & 31;
    const int wm = wid & 1, wn = wid >> 1;
    const int gid = lane >> 2, tig = lane & 3;

    float acc[4][4][4];
    #pragma unroll
    for (int mf = 0; mf < 4; mf++)
        #pragma unroll
        for (int nf = 0; nf < 4; nf++)
            #pragma unroll
            for (int e = 0; e < 4; e++) acc[mf][nf][e] = 0.f;

    uint4 ra[2], rb[2];
    // chunk 0 preload
    #pragma unroll
    for (int q = 0; q < 2; q++) {
        int u = tid + q * 256; int r = u >> 2; int seg = u & 3;
        ra[q] = *(const uint4*)(P + (long)(ib + r) * C_ + seg * 8);
        rb[q] = *(const uint4*)(Q + (long)(jb + r) * C_ + seg * 8);
    }
    #pragma unroll
    for (int q = 0; q < 2; q++) {
        int u = tid + q * 256; int r = u >> 2; int seg = u & 3;
        *(uint4*)(smh + (long)r * PPAD + seg * 8)        = ra[q];
        *(uint4*)(smh + PT_H + (long)r * PPAD + seg * 8) = rb[q];
    }
    __syncthreads();

    for (int i = 0; i < 16; i++) {          // 16 chunks of K=32 halfs
        if (i + 1 < 16) {
            const int k0 = (i + 1) * 32;
            #pragma unroll
            for (int q = 0; q < 2; q++) {
                int u = tid + q * 256; int r = u >> 2; int seg = u & 3;
                ra[q] = *(const uint4*)(P + (long)(ib + r) * C_ + k0 + seg * 8);
                rb[q] = *(const uint4*)(Q + (long)(jb + r) * C_ + k0 + seg * 8);
            }
        }
        const __half* As = smh + (i & 1) * PSTG;
        const __half* Bs = As + PT_H;
        #pragma unroll
        for (int ks = 0; ks < 2; ks++) {    // two k16 steps per chunk
            uint32_t ah[4][4];
            #pragma unroll
            for (int mf = 0; mf < 4; mf++) {
                const __half* ap = As + (long)(wm * 64 + mf * 16 + gid) * PPAD + ks * 16 + tig * 2;
                ah[mf][0] = *(const uint32_t*)ap;
                ah[mf][1] = *(const uint32_t*)(ap + 8 * PPAD);
                ah[mf][2] = *(const uint32_t*)(ap + 8);
                ah[mf][3] = *(const uint32_t*)(ap + 8 * PPAD + 8);
            }
            uint32_t bf[4][2];
            #pragma unroll
            for (int nf = 0; nf < 4; nf++) {
                const __half* bp = Bs + (long)(wn * 32 + nf * 8 + gid) * PPAD + ks * 16 + tig * 2;
                bf[nf][0] = *(const uint32_t*)bp;
                bf[nf][1] = *(const uint32_t*)(bp + 8);
            }
            #pragma unroll
            for (int mf = 0; mf < 4; mf++)
                #pragma unroll
                for (int nf = 0; nf < 4; nf++)
                    mma_f16(acc[mf][nf], ah[mf], bf[nf]);
        }
        if (i + 1 < 16) {
            __half* Ad = smh + ((i + 1) & 1) * PSTG;
            #pragma unroll
            for (int q = 0; q < 2; q++) {
                int u = tid + q * 256; int r = u >> 2; int seg = u & 3;
                *(uint4*)(Ad + (long)r * PPAD + seg * 8)        = ra[q];
                *(uint4*)(Ad + PT_H + (long)r * PPAD + seg * 8) = rb[q];
            }
        }
        __syncthreads();
    }

    __half* D = Dg + (long)b * NSQ;
    const __half* T1 = T1g + (long)b * NSQ;
    const __half* T2 = T2g + (long)b * NSQ;
    #pragma unroll
    for (int mf = 0; mf < 4; mf++) {
        const int r0 = ib + wm * 64 + mf * 16 + gid;
        #pragma unroll
        for (int nf = 0; nf < 4; nf++) {
            const int c0 = jb + wn * 32 + nf * 8 + tig * 2;
            if (MODE == 0) {
                *(__half2*)(D + (long)r0 * C_ + c0)       = __floats2half2_rn(acc[mf][nf][0], acc[mf][nf][1]);
                *(__half2*)(D + (long)(r0 + 8) * C_ + c0) = __floats2half2_rn(acc[mf][nf][2], acc[mf][nf][3]);
            } else {
                float2 t1a = __half22float2(*(const __half2*)(T1 + (long)r0 * C_ + c0));
                float2 t2a = __half22float2(*(const __half2*)(T2 + (long)r0 * C_ + c0));
                float2 t1b = __half22float2(*(const __half2*)(T1 + (long)(r0 + 8) * C_ + c0));
                float2 t2b = __half22float2(*(const __half2*)(T2 + (long)(r0 + 8) * C_ + c0));
                *(__half2*)(D + (long)r0 * C_ + c0) = __floats2half2_rn(
                    2.25f * t1a.x - 1.5f * t2a.x + 0.25f * acc[mf][nf][0],
                    2.25f * t1a.y - 1.5f * t2a.y + 0.25f * acc[mf][nf][1]);
                *(__half2*)(D + (long)(r0 + 8) * C_ + c0) = __floats2half2_rn(
                    2.25f * t1b.x - 1.5f * t2b.x + 0.25f * acc[mf][nf][2],
                    2.25f * t1b.y - 1.5f * t2b.y + 0.25f * acc[mf][nf][3]);
            }
        }
    }
}

// ---------------- fp32 cov -> fp16 T = cov/trace ----------------
__global__ void tohalf_kernel(const float* __restrict__ A, const float* __restrict__ itr,
                              __half* __restrict__ Th)
{
    long i = (long)blockIdx.x * blockDim.x + threadIdx.x;   // per 2 elements
    if (i >= TOT / 2) return;
    int b = (int)((i * 2) / NSQ);
    float s = itr[b];
    float2 f = *(const float2*)(A + i * 2);
    *(__half2*)(Th + i * 2) = __floats2half2_rn(f.x * s, f.y * s);
}

// ---------------- per-row mean of x ----------------
__global__ void mean_kernel(const float* __restrict__ x, float* __restrict__ mean)
{
    int warp = (blockIdx.x * blockDim.x + threadIdx.x) >> 5;
    int lane = threadIdx.x & 31;
    if (warp >= B_*C_) return;
    const float* row = x + (long)warp * M_;
    float s = 0.f;
    for (int k = lane; k < M_; k += 32) s += row[k];
    #pragma unroll
    for (int off = 16; off; off >>= 1) s += __shfl_down_sync(0xffffffffu, s, off);
    if (lane == 0) mean[warp] = s * (1.0f / M_);
}

// ---------------- trace ----------------
__global__ void trace_kernel(const float* __restrict__ A,
                             float* __restrict__ itr, float* __restrict__ str)
{
    __shared__ float sh[512];
    const int b = blockIdx.x;
    const int i = threadIdx.x;
    sh[i] = A[(long)b * NSQ + (long)i * C_ + i];
    __syncthreads();
    for (int off = 256; off; off >>= 1) {
        if (i < off) sh[i] += sh[i + off];
        __syncthreads();
    }
    if (i == 0) { float t = sh[0]; itr[b] = 1.0f / t; str[b] = sqrtf(t); }
}

// ================= Newton-Schulz vector chain on T and S1 (42 matvecs) =================
// Ysqrt/sqrt(tr) = T * W0 * W1..W4; W_k = 1.5I - 0.5 S_k; S_1 explicit (GEMM),
// S_k = S_{k-1} W_{k-1}^2 for k>=2 via state machine with base case S(1)=matvec(S1h).
struct ChainCtx {
    const __half* T;
    const __half* S1;
    float* v;
    float* partial;    // [8*512]
    float* pool;       // [5*512]
    int    tid;
};

__device__ void do_matvec(ChainCtx& c, const __half* Ab)
{
    const int cg = c.tid & 63;
    const int rg = c.tid >> 6;
    const __half* base = Ab + (long)rg * 64 * C_ + cg * 8;
    const float* vs = c.v + rg * 64;

    float a0 = 0.f, a1 = 0.f, a2 = 0.f, a3 = 0.f;
    float a4 = 0.f, a5 = 0.f, a6 = 0.f, a7 = 0.f;
    #pragma unroll 8
    for (int r = 0; r < 64; r++) {
        uint4 q = *(const uint4*)(base + (long)r * C_);
        float s = vs[r];
        float2 f0 = __half22float2(*(__half2*)&q.x);
        float2 f1 = __half22float2(*(__half2*)&q.y);
        float2 f2 = __half22float2(*(__half2*)&q.z);
        float2 f3 = __half22float2(*(__half2*)&q.w);
        a0 = fmaf(s, f0.x, a0);
        a1 = fmaf(s, f0.y, a1);
        a2 = fmaf(s, f1.x, a2);
        a3 = fmaf(s, f1.y, a3);
        a4 = fmaf(s, f2.x, a4);
        a5 = fmaf(s, f2.y, a5);
        a6 = fmaf(s, f3.x, a6);
        a7 = fmaf(s, f3.y, a7);
    }
    *(float4*)(c.partial + rg * 512 + cg * 8)     = make_float4(a0, a1, a2, a3);
    *(float4*)(c.partial + rg * 512 + cg * 8 + 4) = make_float4(a4, a5, a6, a7);
    __syncthreads();
    float sum = 0.f;
    #pragma unroll
    for (int g = 0; g < 8; g++) sum += c.partial[g * 512 + c.tid];
    c.v[c.tid] = sum;
    __syncthreads();
}

// exec_W(k0) for k0>=1: W(k,sp): save; S(k,sp+1); combine.
// S(k,sp): k==1 ? matvec(S1) : { S(k-1,sp); W(k-1,sp); W(k-1,sp); }
__device__ void exec_W(int k0, ChainCtx& c)
{
    int ty[16], kk[16], sp[16], st[16];
    int top = 0;
    ty[0] = 0; kk[0] = k0; sp[0] = 0; st[0] = 0; top = 1;
    while (top > 0) {
        const int i = top - 1;
        if (ty[i] == 0) {                       // W frame
            if (st[i] == 0) {
                float* save = c.pool + sp[i] * 512;
                save[c.tid] = c.v[c.tid];
                __syncthreads();
                st[i] = 1;
                ty[top] = 1; kk[top] = kk[i]; sp[top] = sp[i] + 1; st[top] = 0; top++;
            } else {
                float* save = c.pool + sp[i] * 512;
                float nv = 1.5f * save[c.tid] - 0.5f * c.v[c.tid];
                __syncthreads();
                c.v[c.tid] = nv;
                __syncthreads();
                top--;
            }
        } else {                                // S frame
            if (kk[i] == 1) { do_matvec(c, c.S1); top--; }
            else if (st[i] == 0) {
                st[i] = 1;
                ty[top] = 1; kk[top] = kk[i] - 1; sp[top] = sp[i]; st[top] = 0; top++;
            } else if (st[i] == 1) {
                st[i] = 2;
                ty[top] = 0; kk[top] = kk[i] - 1; sp[top] = sp[i]; st[top] = 0; top++;
            } else if (st[i] == 2) {
                st[i] = 3;
                ty[top] = 0; kk[top] = kk[i] - 1; sp[top] = sp[i]; st[top] = 0; top++;
            } else top--;
        }
    }
}

__global__ void __launch_bounds__(512, 1)
chain_kernel(const __half* __restrict__ Th, const __half* __restrict__ S1h,
             const float* __restrict__ str, float* __restrict__ cs)
{
    __shared__ float v[512];
    __shared__ float partial[8 * 512];
    __shared__ float pool[5 * 512];
    const int b = blockIdx.x;
    const int tid = threadIdx.x;

    ChainCtx c;
    c.T  = Th  + (long)b * NSQ;
    c.S1 = S1h + (long)b * NSQ;
    c.v = v; c.partial = partial; c.pool = pool;
    c.tid = tid;

    v[tid] = 1.0f;
    __syncthreads();

    do_matvec(c, c.T);            // u = 1^T T
    // W0 = 1.5I - 0.5T
    pool[tid] = v[tid];
    __syncthreads();
    do_matvec(c, c.T);
    {
        float nv = 1.5f * pool[tid] - 0.5f * v[tid];
        __syncthreads();
        v[tid] = nv;
        __syncthreads();
    }
    // W1..W4 on explicit S1
    for (int k = 1; k <= 4; k++)
        exec_W(k, c);

    cs[b * C_ + tid] = v[tid] * str[b] * (1.0f / C_);
}

// ---------------- out = cov_sum * x ----------------
__global__ void scale_kernel(const float* __restrict__ x,
                             const float* __restrict__ cs, float* __restrict__ out)
{
    long i4 = (long)blockIdx.x * blockDim.x + threadIdx.x;
    const long total4 = (long)B_ * C_ * M_ / 4;
    if (i4 >= total4) return;
    long e = i4 * 4;
    int bc = (int)(e / M_);
    float s = cs[bc];
    float4 v = *(const float4*)(x + e);
    v.x *= s; v.y *= s; v.z *= s; v.w *= s;
    *(float4*)(out + e) = v;
}

// ---------------- launcher ----------------
extern "C" void kernel_launch(void* const* d_in, const int* in_sizes, int n_in,
                              void* d_out, int out_size)
{
    const float* x = (const float*)d_in[0];
    float* out = (float*)d_out;

    float *A, *mean, *itr, *str, *cs;
    __half *Th, *T2h, *S1h;
    cudaGetSymbolAddress((void**)&A,    g_A);
    cudaGetSymbolAddress((void**)&Th,   g_Th);
    cudaGetSymbolAddress((void**)&T2h,  g_T2h);
    cudaGetSymbolAddress((void**)&S1h,  g_S1h);
    cudaGetSymbolAddress((void**)&mean, g_mean);
    cudaGetSymbolAddress((void**)&itr,  g_itr);
    cudaGetSymbolAddress((void**)&str,  g_str);
    cudaGetSymbolAddress((void**)&cs,   g_cs);

    cudaFuncSetAttribute(cov_gemm, cudaFuncAttributeMaxDynamicSharedMemorySize, GEMM_SMEM);
    cudaFuncSetAttribute(pow_gemm<0>, cudaFuncAttributeMaxDynamicSharedMemorySize, POW_SMEM);
    cudaFuncSetAttribute(pow_gemm<1>, cudaFuncAttributeMaxDynamicSharedMemorySize, POW_SMEM);

    // 1) row means
    mean_kernel<<<(B_*C_ + 7) / 8, 256>>>(x, mean);

    // 2) covariance (fp32 3xTF32, symmetric tiles)
    cov_gemm<<<dim3(10, 1, B_), GT, GEMM_SMEM>>>(x, A, mean);

    // 3) trace, then T = cov/trace in fp16
    trace_kernel<<<B_, 512>>>(A, itr, str);
    tohalf_kernel<<<(int)((TOT / 2 + 255) / 256), 256>>>(A, itr, Th);

    // 4) T^2 = T*T ; S1 = 2.25T - 1.5T^2 + 0.25 T^2*T   (fp16 HMMA)
    pow_gemm<0><<<dim3(4, 4, B_), 256, POW_SMEM>>>(Th, Th, T2h, Th, Th);
    pow_gemm<1><<<dim3(4, 4, B_), 256, POW_SMEM>>>(T2h, Th, S1h, Th, T2h);

    // 5) chain: 42 matvecs (2 on T, 40 on S1)
    chain_kernel<<<B_, 512>>>(Th, S1h, str, cs);

    // 6) out = cov_sum[b][c] * x
    const long total4 = (long)B_ * C_ * M_ / 4;
    scale_kernel<<<(int)((total4 + 255) / 256), 256>>>(x, cs, out);

    (void)in_sizes; (void)n_in; (void)out_size;
}

// round 15
// speedup vs baseline: 9.4806x; 1.0556x over previous
#include <cuda_runtime.h>
#include <cuda_fp16.h>
#include <math.h>
#include <stdint.h>

// Problem constants
#define B_  32
#define C_  512
#define M_  784            // 28*28
#define NSQ (C_*C_)        // 262144
#define TOT ((long)B_*NSQ)

// ---------------- scratch ----------------
__device__ float  g_A  [B_*NSQ];  // covariance matrices (fp32)
__device__ __half g_Th [B_*NSQ];  // T = cov/trace in fp16
__device__ __half g_P2 [B_*NSQ];  // scratch: squares (T^2, then S1^2)
__device__ __half g_S1h[B_*NSQ];  // S1 = 2.25T - 1.5T^2 + 0.25T^3
__device__ __half g_S2h[B_*NSQ];  // S2 = 2.25S1 - 1.5S1^2 + 0.25S1^3
__device__ float  g_mean[B_*C_];
__device__ float  g_itr[B_];      // 1/trace
__device__ float  g_str[B_];      // sqrt(trace)
__device__ float  g_cs [B_*C_];   // final column means

// ================= warp-level MMA =================
__device__ __forceinline__ void mma_tf32(float* c, const uint32_t* a, const uint32_t* b) {
    asm volatile("mma.sync.aligned.m16n8k8.row.col.f32.tf32.tf32.f32 "
        "{%0,%1,%2,%3}, {%4,%5,%6,%7}, {%8,%9}, {%0,%1,%2,%3};"
        : "+f"(c[0]), "+f"(c[1]), "+f"(c[2]), "+f"(c[3])
        : "r"(a[0]), "r"(a[1]), "r"(a[2]), "r"(a[3]), "r"(b[0]), "r"(b[1]));
}
__device__ __forceinline__ void mma_f16(float* c, const uint32_t* a, const uint32_t* b) {
    asm volatile("mma.sync.aligned.m16n8k16.row.col.f32.f16.f16.f32 "
        "{%0,%1,%2,%3}, {%4,%5,%6,%7}, {%8,%9}, {%0,%1,%2,%3};"
        : "+f"(c[0]), "+f"(c[1]), "+f"(c[2]), "+f"(c[3])
        : "r"(a[0]), "r"(a[1]), "r"(a[2]), "r"(a[3]), "r"(b[0]), "r"(b[1]));
}
#define HI_MASK 0xFFFFE000u
__device__ __forceinline__ void split_tf32(float x, uint32_t& hi, uint32_t& lo) {
    uint32_t xb = __float_as_uint(x);
    hi = xb & HI_MASK;
    float lof = x - __uint_as_float(hi);
    lo = __float_as_uint(lof) & HI_MASK;
}

// ================= covariance GEMM (fp32, 3xTF32, upper-tri tiles) =================
#define KCH  32
#define GT   256
#define APAD 36
#define ATILE_F (128*APAD)
#define STAGE_F (2*ATILE_F)
#define GEMM_SMEM (2*STAGE_F*4)   // 73728 bytes

__constant__ int c_bi[10] = {0,0,0,0,1,1,1,2,2,3};
__constant__ int c_bj[10] = {0,1,2,3,1,2,3,2,3,3};

__global__ void __launch_bounds__(GT)
cov_gemm(const float* __restrict__ xg, float* __restrict__ Cg,
         const float* __restrict__ meang)
{
    extern __shared__ float sm[];
    const int tid = threadIdx.x;
    const int b = blockIdx.z;
    const float* A  = xg + (long)b * C_ * M_;
    float*       C  = Cg + (long)b * NSQ;
    const int ib = c_bi[blockIdx.x] * 128;
    const int jb = c_bj[blockIdx.x] * 128;
    const int K = M_;
    const float covInvM = 1.0f / M_;

    const int wid = tid >> 5, lane = tid & 31;
    const int wm = wid & 1, wn = wid >> 1;
    const int gid = lane >> 2, tig = lane & 3;

    float acc[4][4][4];
    #pragma unroll
    for (int mf = 0; mf < 4; mf++)
        #pragma unroll
        for (int nf = 0; nf < 4; nf++)
            #pragma unroll
            for (int e = 0; e < 4; e++) acc[mf][nf][e] = 0.f;

    const int NC = (K + KCH - 1) / KCH;
    float4 ra[4], rb[4];

    #pragma unroll
    for (int q = 0; q < 4; q++) {
        int f = tid + q * GT; int r = f >> 3; int k = (f & 7) * 4;
        ra[q] = (k < K) ? *(const float4*)(A + (long)(ib + r) * M_ + k) : make_float4(0,0,0,0);
        rb[q] = (k < K) ? *(const float4*)(A + (long)(jb + r) * M_ + k) : make_float4(0,0,0,0);
    }
    #pragma unroll
    for (int q = 0; q < 4; q++) {
        int f = tid + q * GT; int r = f >> 3; int c = (f & 7) * 4;
        *(float4*)(sm + (long)r * APAD + c)           = ra[q];
        *(float4*)(sm + ATILE_F + (long)r * APAD + c) = rb[q];
    }
    __syncthreads();

    for (int i = 0; i < NC; i++) {
        if (i + 1 < NC) {
            const int k0 = (i + 1) * KCH;
            #pragma unroll
            for (int q = 0; q < 4; q++) {
                int f = tid + q * GT; int r = f >> 3; int k = k0 + (f & 7) * 4;
                ra[q] = (k < K) ? *(const float4*)(A + (long)(ib + r) * M_ + k) : make_float4(0,0,0,0);
                rb[q] = (k < K) ? *(const float4*)(A + (long)(jb + r) * M_ + k) : make_float4(0,0,0,0);
            }
        }
        const float* As = sm + (i & 1) * STAGE_F;
        const float* Bs = As + ATILE_F;
        #pragma unroll
        for (int ks = 0; ks < 4; ks++) {
            uint32_t ah[4][4], al[4][4];
            #pragma unroll
            for (int mf = 0; mf < 4; mf++) {
                int base = (wm * 64 + mf * 16 + gid) * APAD + ks * 8 + tig;
                split_tf32(As[base],                ah[mf][0], al[mf][0]);
                split_tf32(As[base + 8 * APAD],     ah[mf][1], al[mf][1]);
                split_tf32(As[base + 4],            ah[mf][2], al[mf][2]);
                split_tf32(As[base + 8 * APAD + 4], ah[mf][3], al[mf][3]);
            }
            uint32_t bh[4][2], bl[4][2];
            #pragma unroll
            for (int nf = 0; nf < 4; nf++) {
                int base = (wn * 32 + nf * 8 + gid) * APAD + ks * 8 + tig;
                split_tf32(Bs[base],     bh[nf][0], bl[nf][0]);
                split_tf32(Bs[base + 4], bh[nf][1], bl[nf][1]);
            }
            #pragma unroll
            for (int mf = 0; mf < 4; mf++)
                #pragma unroll
                for (int nf = 0; nf < 4; nf++) {
                    mma_tf32(acc[mf][nf], ah[mf], bh[nf]);
                    mma_tf32(acc[mf][nf], ah[mf], bl[nf]);
                    mma_tf32(acc[mf][nf], al[mf], bh[nf]);
                }
        }
        if (i + 1 < NC) {
            float* Ad = sm + ((i + 1) & 1) * STAGE_F;
            #pragma unroll
            for (int q = 0; q < 4; q++) {
                int f = tid + q * GT; int r = f >> 3; int c = (f & 7) * 4;
                *(float4*)(Ad + (long)r * APAD + c)           = ra[q];
                *(float4*)(Ad + ATILE_F + (long)r * APAD + c) = rb[q];
            }
        }
        __syncthreads();
    }

    const bool offdiag = (ib != jb);
    #pragma unroll
    for (int mf = 0; mf < 4; mf++) {
        const int row0 = ib + wm * 64 + mf * 16 + gid;
        float mi0 = meang[b * C_ + row0];
        float mi1 = meang[b * C_ + row0 + 8];
        #pragma unroll
        for (int nf = 0; nf < 4; nf++) {
            const int col0 = jb + wn * 32 + nf * 8 + tig * 2;
            float mj0 = meang[b * C_ + col0], mj1 = meang[b * C_ + col0 + 1];
            float c0 = acc[mf][nf][0] * covInvM - mi0 * mj0;
            float c1 = acc[mf][nf][1] * covInvM - mi0 * mj1;
            float c2 = acc[mf][nf][2] * covInvM - mi1 * mj0;
            float c3 = acc[mf][nf][3] * covInvM - mi1 * mj1;
            *(float2*)(C + (long)row0 * C_ + col0)       = make_float2(c0, c1);
            *(float2*)(C + (long)(row0 + 8) * C_ + col0) = make_float2(c2, c3);
            if (offdiag) {
                C[(long)col0 * C_ + row0]           = c0;
                C[(long)(col0 + 1) * C_ + row0]     = c1;
                C[(long)col0 * C_ + row0 + 8]       = c2;
                C[(long)(col0 + 1) * C_ + row0 + 8] = c3;
            }
        }
    }
}

// ================= fp16 power GEMM: D = P * Q^T =================
// MODE 0: D = fp16(acc)
// MODE 1: D = fp16(2.25*T1 - 1.5*T2 + 0.25*acc)   (cubic NS combine)
#define PPAD 40
#define PT_H (128*PPAD)
#define PSTG (2*PT_H)
#define POW_SMEM (2*PSTG*2)       // 40960 bytes

template<int MODE>
__global__ void __launch_bounds__(256)
pow_gemm(const __half* __restrict__ Pg, const __half* __restrict__ Qg,
         __half* __restrict__ Dg,
         const __half* __restrict__ T1g, const __half* __restrict__ T2g)
{
    extern __shared__ __half smh[];
    const int tid = threadIdx.x;
    const int b = blockIdx.z;
    const __half* P = Pg + (long)b * NSQ;
    const __half* Q = Qg + (long)b * NSQ;
    const int ib = blockIdx.y * 128, jb = blockIdx.x * 128;

    const int wid = tid >> 5, lane = tid & 31;
    const int wm = wid & 1, wn = wid >> 1;
    const int gid = lane >> 2, tig = lane & 3;

    float acc[4][4][4];
    #pragma unroll
    for (int mf = 0; mf < 4; mf++)
        #pragma unroll
        for (int nf = 0; nf < 4; nf++)
            #pragma unroll
            for (int e = 0; e < 4; e++) acc[mf][nf][e] = 0.f;

    uint4 ra[2], rb[2];
    #pragma unroll
    for (int q = 0; q < 2; q++) {
        int u = tid + q * 256; int r = u >> 2; int seg = u & 3;
        ra[q] = *(const uint4*)(P + (long)(ib + r) * C_ + seg * 8);
        rb[q] = *(const uint4*)(Q + (long)(jb + r) * C_ + seg * 8);
    }
    #pragma unroll
    for (int q = 0; q < 2; q++) {
        int u = tid + q * 256; int r = u >> 2; int seg = u & 3;
        *(uint4*)(smh + (long)r * PPAD + seg * 8)        = ra[q];
        *(uint4*)(smh + PT_H + (long)r * PPAD + seg * 8) = rb[q];
    }
    __syncthreads();

    for (int i = 0; i < 16; i++) {
        if (i + 1 < 16) {
            const int k0 = (i + 1) * 32;
            #pragma unroll
            for (int q = 0; q < 2; q++) {
                int u = tid + q * 256; int r = u >> 2; int seg = u & 3;
                ra[q] = *(const uint4*)(P + (long)(ib + r) * C_ + k0 + seg * 8);
                rb[q] = *(const uint4*)(Q + (long)(jb + r) * C_ + k0 + seg * 8);
            }
        }
        const __half* As = smh + (i & 1) * PSTG;
        const __half* Bs = As + PT_H;
        #pragma unroll
        for (int ks = 0; ks < 2; ks++) {
            uint32_t ah[4][4];
            #pragma unroll
            for (int mf = 0; mf < 4; mf++) {
                const __half* ap = As + (long)(wm * 64 + mf * 16 + gid) * PPAD + ks * 16 + tig * 2;
                ah[mf][0] = *(const uint32_t*)ap;
                ah[mf][1] = *(const uint32_t*)(ap + 8 * PPAD);
                ah[mf][2] = *(const uint32_t*)(ap + 8);
                ah[mf][3] = *(const uint32_t*)(ap + 8 * PPAD + 8);
            }
            uint32_t bf[4][2];
            #pragma unroll
            for (int nf = 0; nf < 4; nf++) {
                const __half* bp = Bs + (long)(wn * 32 + nf * 8 + gid) * PPAD + ks * 16 + tig * 2;
                bf[nf][0] = *(const uint32_t*)bp;
                bf[nf][1] = *(const uint32_t*)(bp + 8);
            }
            #pragma unroll
            for (int mf = 0; mf < 4; mf++)
                #pragma unroll
                for (int nf = 0; nf < 4; nf++)
                    mma_f16(acc[mf][nf], ah[mf], bf[nf]);
        }
        if (i + 1 < 16) {
            __half* Ad = smh + ((i + 1) & 1) * PSTG;
            #pragma unroll
            for (int q = 0; q < 2; q++) {
                int u = tid + q * 256; int r = u >> 2; int seg = u & 3;
                *(uint4*)(Ad + (long)r * PPAD + seg * 8)        = ra[q];
                *(uint4*)(Ad + PT_H + (long)r * PPAD + seg * 8) = rb[q];
            }
        }
        __syncthreads();
    }

    __half* D = Dg + (long)b * NSQ;
    const __half* T1 = T1g + (long)b * NSQ;
    const __half* T2 = T2g + (long)b * NSQ;
    #pragma unroll
    for (int mf = 0; mf < 4; mf++) {
        const int r0 = ib + wm * 64 + mf * 16 + gid;
        #pragma unroll
        for (int nf = 0; nf < 4; nf++) {
            const int c0 = jb + wn * 32 + nf * 8 + tig * 2;
            if (MODE == 0) {
                *(__half2*)(D + (long)r0 * C_ + c0)       = __floats2half2_rn(acc[mf][nf][0], acc[mf][nf][1]);
                *(__half2*)(D + (long)(r0 + 8) * C_ + c0) = __floats2half2_rn(acc[mf][nf][2], acc[mf][nf][3]);
            } else {
                float2 t1a = __half22float2(*(const __half2*)(T1 + (long)r0 * C_ + c0));
                float2 t2a = __half22float2(*(const __half2*)(T2 + (long)r0 * C_ + c0));
                float2 t1b = __half22float2(*(const __half2*)(T1 + (long)(r0 + 8) * C_ + c0));
                float2 t2b = __half22float2(*(const __half2*)(T2 + (long)(r0 + 8) * C_ + c0));
                *(__half2*)(D + (long)r0 * C_ + c0) = __floats2half2_rn(
                    2.25f * t1a.x - 1.5f * t2a.x + 0.25f * acc[mf][nf][0],
                    2.25f * t1a.y - 1.5f * t2a.y + 0.25f * acc[mf][nf][1]);
                *(__half2*)(D + (long)(r0 + 8) * C_ + c0) = __floats2half2_rn(
                    2.25f * t1b.x - 1.5f * t2b.x + 0.25f * acc[mf][nf][2],
                    2.25f * t1b.y - 1.5f * t2b.y + 0.25f * acc[mf][nf][3]);
            }
        }
    }
}

// ---------------- fp32 cov -> fp16 T = cov/trace ----------------
__global__ void tohalf_kernel(const float* __restrict__ A, const float* __restrict__ itr,
                              __half* __restrict__ Th)
{
    long i = (long)blockIdx.x * blockDim.x + threadIdx.x;
    if (i >= TOT / 2) return;
    int b = (int)((i * 2) / NSQ);
    float s = itr[b];
    float2 f = *(const float2*)(A + i * 2);
    *(__half2*)(Th + i * 2) = __floats2half2_rn(f.x * s, f.y * s);
}

// ---------------- per-row mean of x ----------------
__global__ void mean_kernel(const float* __restrict__ x, float* __restrict__ mean)
{
    int warp = (blockIdx.x * blockDim.x + threadIdx.x) >> 5;
    int lane = threadIdx.x & 31;
    if (warp >= B_*C_) return;
    const float* row = x + (long)warp * M_;
    float s = 0.f;
    for (int k = lane; k < M_; k += 32) s += row[k];
    #pragma unroll
    for (int off = 16; off; off >>= 1) s += __shfl_down_sync(0xffffffffu, s, off);
    if (lane == 0) mean[warp] = s * (1.0f / M_);
}

// ---------------- trace ----------------
__global__ void trace_kernel(const float* __restrict__ A,
                             float* __restrict__ itr, float* __restrict__ str)
{
    __shared__ float sh[512];
    const int b = blockIdx.x;
    const int i = threadIdx.x;
    sh[i] = A[(long)b * NSQ + (long)i * C_ + i];
    __syncthreads();
    for (int off = 256; off; off >>= 1) {
        if (i < off) sh[i] += sh[i + off];
        __syncthreads();
    }
    if (i == 0) { float t = sh[0]; itr[b] = 1.0f / t; str[b] = sqrtf(t); }
}

// ================= Newton-Schulz vector chain: 16 matvecs =================
// u = 1^T T; W0 (T); W1 (S1); W2..W4 in S2-units (1+3+9 = 13 matvecs).
struct ChainCtx {
    const __half* S2;
    float* v;
    float* partial;    // [8*512]
    float* pool;       // [5*512]
    int    tid;
};

__device__ void mv(const __half* Ab, float* v, float* partial, int tid)
{
    const int cg = tid & 63;
    const int rg = tid >> 6;
    const __half* base = Ab + (long)rg * 64 * C_ + cg * 8;
    const float* vs = v + rg * 64;

    float a0 = 0.f, a1 = 0.f, a2 = 0.f, a3 = 0.f;
    float a4 = 0.f, a5 = 0.f, a6 = 0.f, a7 = 0.f;
    #pragma unroll 8
    for (int r = 0; r < 64; r++) {
        uint4 q = *(const uint4*)(base + (long)r * C_);
        float s = vs[r];
        float2 f0 = __half22float2(*(__half2*)&q.x);
        float2 f1 = __half22float2(*(__half2*)&q.y);
        float2 f2 = __half22float2(*(__half2*)&q.z);
        float2 f3 = __half22float2(*(__half2*)&q.w);
        a0 = fmaf(s, f0.x, a0);
        a1 = fmaf(s, f0.y, a1);
        a2 = fmaf(s, f1.x, a2);
        a3 = fmaf(s, f1.y, a3);
        a4 = fmaf(s, f2.x, a4);
        a5 = fmaf(s, f2.y, a5);
        a6 = fmaf(s, f3.x, a6);
        a7 = fmaf(s, f3.y, a7);
    }
    *(float4*)(partial + rg * 512 + cg * 8)     = make_float4(a0, a1, a2, a3);
    *(float4*)(partial + rg * 512 + cg * 8 + 4) = make_float4(a4, a5, a6, a7);
    __syncthreads();
    float sum = 0.f;
    #pragma unroll
    for (int g = 0; g < 8; g++) sum += partial[g * 512 + tid];
    v[tid] = sum;
    __syncthreads();
}

// applyW over base matrix: save; v = v*Ab; combine.
__device__ void applyW_direct(const __half* Ab, float* v, float* partial,
                              float* save, int tid)
{
    save[tid] = v[tid];
    __syncthreads();
    mv(Ab, v, partial, tid);
    float nv = 1.5f * save[tid] - 0.5f * v[tid];
    __syncthreads();
    v[tid] = nv;
    __syncthreads();
}

// exec_W(k0) for k>=2 in S2 units: base case S(2) = matvec(S2).
__device__ void exec_W(int k0, ChainCtx& c)
{
    int ty[16], kk[16], sp[16], st[16];
    int top = 0;
    ty[0] = 0; kk[0] = k0; sp[0] = 0; st[0] = 0; top = 1;
    while (top > 0) {
        const int i = top - 1;
        if (ty[i] == 0) {                       // W frame
            if (st[i] == 0) {
                float* save = c.pool + sp[i] * 512;
                save[c.tid] = c.v[c.tid];
                __syncthreads();
                st[i] = 1;
                ty[top] = 1; kk[top] = kk[i]; sp[top] = sp[i] + 1; st[top] = 0; top++;
            } else {
                float* save = c.pool + sp[i] * 512;
                float nv = 1.5f * save[c.tid] - 0.5f * c.v[c.tid];
                __syncthreads();
                c.v[c.tid] = nv;
                __syncthreads();
                top--;
            }
        } else {                                // S frame
            if (kk[i] == 2) { mv(c.S2, c.v, c.partial, c.tid); top--; }
            else if (st[i] == 0) {
                st[i] = 1;
                ty[top] = 1; kk[top] = kk[i] - 1; sp[top] = sp[i]; st[top] = 0; top++;
            } else if (st[i] == 1) {
                st[i] = 2;
                ty[top] = 0; kk[top] = kk[i] - 1; sp[top] = sp[i]; st[top] = 0; top++;
            } else if (st[i] == 2) {
                st[i] = 3;
                ty[top] = 0; kk[top] = kk[i] - 1; sp[top] = sp[i]; st[top] = 0; top++;
            } else top--;
        }
    }
}

__global__ void __launch_bounds__(512, 1)
chain_kernel(const __half* __restrict__ Th, const __half* __restrict__ S1h,
             const __half* __restrict__ S2h,
             const float* __restrict__ str, float* __restrict__ cs)
{
    __shared__ float v[512];
    __shared__ float partial[8 * 512];
    __shared__ float pool[5 * 512];
    const int b = blockIdx.x;
    const int tid = threadIdx.x;

    const __half* T  = Th  + (long)b * NSQ;
    const __half* S1 = S1h + (long)b * NSQ;

    ChainCtx c;
    c.S2 = S2h + (long)b * NSQ;
    c.v = v; c.partial = partial; c.pool = pool;
    c.tid = tid;

    v[tid] = 1.0f;
    __syncthreads();

    mv(T, v, partial, tid);                          // u = 1^T T
    applyW_direct(T,  v, partial, pool, tid);        // W0
    applyW_direct(S1, v, partial, pool, tid);        // W1
    for (int k = 2; k <= 4; k++)                     // W2..W4 on S2
        exec_W(k, c);

    cs[b * C_ + tid] = v[tid] * str[b] * (1.0f / C_);
}

// ---------------- out = cov_sum * x ----------------
__global__ void scale_kernel(const float* __restrict__ x,
                             const float* __restrict__ cs, float* __restrict__ out)
{
    long i4 = (long)blockIdx.x * blockDim.x + threadIdx.x;
    const long total4 = (long)B_ * C_ * M_ / 4;
    if (i4 >= total4) return;
    long e = i4 * 4;
    int bc = (int)(e / M_);
    float s = cs[bc];
    float4 v = *(const float4*)(x + e);
    v.x *= s; v.y *= s; v.z *= s; v.w *= s;
    *(float4*)(out + e) = v;
}

// ---------------- launcher ----------------
extern "C" void kernel_launch(void* const* d_in, const int* in_sizes, int n_in,
                              void* d_out, int out_size)
{
    const float* x = (const float*)d_in[0];
    float* out = (float*)d_out;

    float *A, *mean, *itr, *str, *cs;
    __half *Th, *P2, *S1h, *S2h;
    cudaGetSymbolAddress((void**)&A,    g_A);
    cudaGetSymbolAddress((void**)&Th,   g_Th);
    cudaGetSymbolAddress((void**)&P2,   g_P2);
    cudaGetSymbolAddress((void**)&S1h,  g_S1h);
    cudaGetSymbolAddress((void**)&S2h,  g_S2h);
    cudaGetSymbolAddress((void**)&mean, g_mean);
    cudaGetSymbolAddress((void**)&itr,  g_itr);
    cudaGetSymbolAddress((void**)&str,  g_str);
    cudaGetSymbolAddress((void**)&cs,   g_cs);

    cudaFuncSetAttribute(cov_gemm, cudaFuncAttributeMaxDynamicSharedMemorySize, GEMM_SMEM);
    cudaFuncSetAttribute(pow_gemm<0>, cudaFuncAttributeMaxDynamicSharedMemorySize, POW_SMEM);
    cudaFuncSetAttribute(pow_gemm<1>, cudaFuncAttributeMaxDynamicSharedMemorySize, POW_SMEM);

    // 1) row means
    mean_kernel<<<(B_*C_ + 7) / 8, 256>>>(x, mean);

    // 2) covariance (fp32 3xTF32, symmetric tiles)
    cov_gemm<<<dim3(10, 1, B_), GT, GEMM_SMEM>>>(x, A, mean);

    // 3) trace, then T = cov/trace in fp16
    trace_kernel<<<B_, 512>>>(A, itr, str);
    tohalf_kernel<<<(int)((TOT / 2 + 255) / 256), 256>>>(A, itr, Th);

    // 4) S1 = 2.25T - 1.5T^2 + 0.25T^3 ; S2 = 2.25S1 - 1.5S1^2 + 0.25S1^3
    const dim3 pg(4, 4, B_);
    pow_gemm<0><<<pg, 256, POW_SMEM>>>(Th,  Th,  P2,  Th,  Th);   // P2 = T^2
    pow_gemm<1><<<pg, 256, POW_SMEM>>>(P2,  Th,  S1h, Th,  P2);   // S1
    pow_gemm<0><<<pg, 256, POW_SMEM>>>(S1h, S1h, P2,  S1h, S1h);  // P2 = S1^2
    pow_gemm<1><<<pg, 256, POW_SMEM>>>(P2,  S1h, S2h, S1h, P2);   // S2

    // 5) chain: 16 matvecs (2 T, 1 S1, 13 S2)
    chain_kernel<<<B_, 512>>>(Th, S1h, S2h, str, cs);

    // 6) out = cov_sum[b][c] * x
    const long total4 = (long)B_ * C_ * M_ / 4;
    scale_kernel<<<(int)((total4 + 255) / 256), 256>>>(x, cs, out);

    (void)in_sizes; (void)n_in; (void)out_size;
}

// round 16
// speedup vs baseline: 11.2650x; 1.1882x over previous
#include <cuda_runtime.h>
#include <cuda_fp16.h>
#include <math.h>
#include <stdint.h>

// Problem constants
#define B_  32
#define C_  512
#define M_  784            // 28*28
#define MPAD 800           // padded K for fp16 split x (25 chunks of 32)
#define NSQ (C_*C_)        // 262144
#define TOT ((long)B_*NSQ)

// ---------------- scratch ----------------
__device__ __half g_xh [B_*C_*MPAD]; // x hi halves (zero-padded)
__device__ __half g_xl [B_*C_*MPAD]; // x lo halves
__device__ __half g_Th [B_*NSQ];     // T = cov/trace in fp16
__device__ __half g_P2 [B_*NSQ];     // scratch squares
__device__ __half g_S1h[B_*NSQ];
__device__ __half g_S2h[B_*NSQ];
__device__ float  g_mean[B_*C_];
__device__ float  g_ssq [B_*C_];     // per-row sum of squares
__device__ float  g_itr[B_];
__device__ float  g_str[B_];
__device__ float  g_cs [B_*C_];

__device__ __forceinline__ void mma_f16(float* c, const uint32_t* a, const uint32_t* b) {
    asm volatile("mma.sync.aligned.m16n8k16.row.col.f32.f16.f16.f32 "
        "{%0,%1,%2,%3}, {%4,%5,%6,%7}, {%8,%9}, {%0,%1,%2,%3};"
        : "+f"(c[0]), "+f"(c[1]), "+f"(c[2]), "+f"(c[3])
        : "r"(a[0]), "r"(a[1]), "r"(a[2]), "r"(a[3]), "r"(b[0]), "r"(b[1]));
}

__constant__ int c_bi[10] = {0,0,0,0,1,1,1,2,2,3};
__constant__ int c_bj[10] = {0,1,2,3,1,2,3,2,3,3};

// ================= split x into fp16 hi/lo (padded) =================
__global__ void splitx_kernel(const float* __restrict__ x,
                              __half* __restrict__ xh, __half* __restrict__ xl)
{
    long g = (long)blockIdx.x * blockDim.x + threadIdx.x;   // one uint4 (8 halfs)
    const long total = (long)B_ * C_ * (MPAD / 8);
    if (g >= total) return;
    long row = g / (MPAD / 8);
    int grp = (int)(g % (MPAD / 8));
    __half hi[8], lo[8];
    if (grp < 98) {   // groups 0..97 are fully inside M_=784
        const float* src = x + row * M_ + grp * 8;
        #pragma unroll
        for (int e = 0; e < 8; e++) {
            float v = src[e];
            __half h = __float2half_rn(v);
            hi[e] = h;
            lo[e] = __float2half_rn(v - __half2float(h));
        }
    } else {
        #pragma unroll
        for (int e = 0; e < 8; e++) { hi[e] = __float2half_rn(0.f); lo[e] = hi[e]; }
    }
    *(uint4*)(xh + row * MPAD + grp * 8) = *(uint4*)hi;
    *(uint4*)(xl + row * MPAD + grp * 8) = *(uint4*)lo;
}

// ================= per-row mean and sum-of-squares =================
__global__ void mean_kernel(const float* __restrict__ x, float* __restrict__ mean,
                            float* __restrict__ ssq)
{
    int warp = (blockIdx.x * blockDim.x + threadIdx.x) >> 5;
    int lane = threadIdx.x & 31;
    if (warp >= B_*C_) return;
    const float* row = x + (long)warp * M_;
    float s = 0.f, q = 0.f;
    for (int k = lane; k < M_; k += 32) { float v = row[k]; s += v; q = fmaf(v, v, q); }
    #pragma unroll
    for (int off = 16; off; off >>= 1) {
        s += __shfl_down_sync(0xffffffffu, s, off);
        q += __shfl_down_sync(0xffffffffu, q, off);
    }
    if (lane == 0) { mean[warp] = s * (1.0f / M_); ssq[warp] = q; }
}

// ================= trace from mean/ssq (before cov GEMM) =================
__global__ void tracex_kernel(const float* __restrict__ mean, const float* __restrict__ ssq,
                              float* __restrict__ itr, float* __restrict__ str)
{
    __shared__ float sh[512];
    const int b = blockIdx.x;
    const int i = threadIdx.x;
    float m = mean[b * C_ + i];
    sh[i] = ssq[b * C_ + i] * (1.0f / M_) - m * m;
    __syncthreads();
    for (int off = 256; off; off >>= 1) {
        if (i < off) sh[i] += sh[i + off];
        __syncthreads();
    }
    if (i == 0) { float t = sh[0]; itr[b] = 1.0f / t; str[b] = sqrtf(t); }
}

// ================= cov GEMM in split-fp16: T = ((x x^T)/M - mean mean^T) * itr ==========
// 3-term: hi*hi + hi*lo + lo*hi ; upper-tri tiles, fp16 output + mirror.
#define HPAD 40
#define HT (128*HPAD)                 // halfs per tile
#define HSTG (4*HT)                   // Ahi, Alo, Bhi, Blo
#define COV_SMEM (2*HSTG*2)           // 81920 bytes

__global__ void __launch_bounds__(256)
cov_gemm_h(const __half* __restrict__ xhg, const __half* __restrict__ xlg,
           __half* __restrict__ Tg, const float* __restrict__ meang,
           const float* __restrict__ itrg)
{
    extern __shared__ __half smh[];
    const int tid = threadIdx.x;
    const int b = blockIdx.z;
    const __half* XH = xhg + (long)b * C_ * MPAD;
    const __half* XL = xlg + (long)b * C_ * MPAD;
    const int ib = c_bi[blockIdx.x] * 128;
    const int jb = c_bj[blockIdx.x] * 128;
    const float covInvM = 1.0f / M_;
    const float itr = itrg[b];

    const int wid = tid >> 5, lane = tid & 31;
    const int wm = wid & 1, wn = wid >> 1;
    const int gid = lane >> 2, tig = lane & 3;

    float acc[4][4][4];
    #pragma unroll
    for (int mf = 0; mf < 4; mf++)
        #pragma unroll
        for (int nf = 0; nf < 4; nf++)
            #pragma unroll
            for (int e = 0; e < 4; e++) acc[mf][nf][e] = 0.f;

    uint4 rah[2], ral[2], rbh[2], rbl[2];
    #pragma unroll
    for (int q = 0; q < 2; q++) {
        int u = tid + q * 256; int r = u >> 2; int seg = u & 3;
        rah[q] = *(const uint4*)(XH + (long)(ib + r) * MPAD + seg * 8);
        ral[q] = *(const uint4*)(XL + (long)(ib + r) * MPAD + seg * 8);
        rbh[q] = *(const uint4*)(XH + (long)(jb + r) * MPAD + seg * 8);
        rbl[q] = *(const uint4*)(XL + (long)(jb + r) * MPAD + seg * 8);
    }
    #pragma unroll
    for (int q = 0; q < 2; q++) {
        int u = tid + q * 256; int r = u >> 2; int seg = u & 3;
        *(uint4*)(smh + 0*HT + (long)r * HPAD + seg * 8) = rah[q];
        *(uint4*)(smh + 1*HT + (long)r * HPAD + seg * 8) = ral[q];
        *(uint4*)(smh + 2*HT + (long)r * HPAD + seg * 8) = rbh[q];
        *(uint4*)(smh + 3*HT + (long)r * HPAD + seg * 8) = rbl[q];
    }
    __syncthreads();

    const int NCH = MPAD / 32;   // 25 chunks
    for (int i = 0; i < NCH; i++) {
        if (i + 1 < NCH) {
            const int k0 = (i + 1) * 32;
            #pragma unroll
            for (int q = 0; q < 2; q++) {
                int u = tid + q * 256; int r = u >> 2; int seg = u & 3;
                rah[q] = *(const uint4*)(XH + (long)(ib + r) * MPAD + k0 + seg * 8);
                ral[q] = *(const uint4*)(XL + (long)(ib + r) * MPAD + k0 + seg * 8);
                rbh[q] = *(const uint4*)(XH + (long)(jb + r) * MPAD + k0 + seg * 8);
                rbl[q] = *(const uint4*)(XL + (long)(jb + r) * MPAD + k0 + seg * 8);
            }
        }
        const __half* S = smh + (i & 1) * HSTG;
        #pragma unroll
        for (int ks = 0; ks < 2; ks++) {
            uint32_t ah[4][4], al[4][4];
            #pragma unroll
            for (int mf = 0; mf < 4; mf++) {
                long off = (long)(wm * 64 + mf * 16 + gid) * HPAD + ks * 16 + tig * 2;
                const __half* ph = S + 0*HT + off;
                const __half* pl = S + 1*HT + off;
                ah[mf][0] = *(const uint32_t*)ph;
                ah[mf][1] = *(const uint32_t*)(ph + 8 * HPAD);
                ah[mf][2] = *(const uint32_t*)(ph + 8);
                ah[mf][3] = *(const uint32_t*)(ph + 8 * HPAD + 8);
                al[mf][0] = *(const uint32_t*)pl;
                al[mf][1] = *(const uint32_t*)(pl + 8 * HPAD);
                al[mf][2] = *(const uint32_t*)(pl + 8);
                al[mf][3] = *(const uint32_t*)(pl + 8 * HPAD + 8);
            }
            uint32_t bh[4][2], bl[4][2];
            #pragma unroll
            for (int nf = 0; nf < 4; nf++) {
                long off = (long)(wn * 32 + nf * 8 + gid) * HPAD + ks * 16 + tig * 2;
                const __half* ph = S + 2*HT + off;
                const __half* pl = S + 3*HT + off;
                bh[nf][0] = *(const uint32_t*)ph;
                bh[nf][1] = *(const uint32_t*)(ph + 8);
                bl[nf][0] = *(const uint32_t*)pl;
                bl[nf][1] = *(const uint32_t*)(pl + 8);
            }
            #pragma unroll
            for (int mf = 0; mf < 4; mf++)
                #pragma unroll
                for (int nf = 0; nf < 4; nf++) {
                    mma_f16(acc[mf][nf], ah[mf], bh[nf]);
                    mma_f16(acc[mf][nf], ah[mf], bl[nf]);
                    mma_f16(acc[mf][nf], al[mf], bh[nf]);
                }
        }
        if (i + 1 < NCH) {
            __half* D = smh + ((i + 1) & 1) * HSTG;
            #pragma unroll
            for (int q = 0; q < 2; q++) {
                int u = tid + q * 256; int r = u >> 2; int seg = u & 3;
                *(uint4*)(D + 0*HT + (long)r * HPAD + seg * 8) = rah[q];
                *(uint4*)(D + 1*HT + (long)r * HPAD + seg * 8) = ral[q];
                *(uint4*)(D + 2*HT + (long)r * HPAD + seg * 8) = rbh[q];
                *(uint4*)(D + 3*HT + (long)r * HPAD + seg * 8) = rbl[q];
            }
        }
        __syncthreads();
    }

    __half* T = Tg + (long)b * NSQ;
    const bool offdiag = (ib != jb);
    #pragma unroll
    for (int mf = 0; mf < 4; mf++) {
        const int r0 = ib + wm * 64 + mf * 16 + gid;
        float mi0 = meang[b * C_ + r0];
        float mi1 = meang[b * C_ + r0 + 8];
        #pragma unroll
        for (int nf = 0; nf < 4; nf++) {
            const int c0 = jb + wn * 32 + nf * 8 + tig * 2;
            float mj0 = meang[b * C_ + c0], mj1 = meang[b * C_ + c0 + 1];
            float t0 = (acc[mf][nf][0] * covInvM - mi0 * mj0) * itr;
            float t1 = (acc[mf][nf][1] * covInvM - mi0 * mj1) * itr;
            float t2 = (acc[mf][nf][2] * covInvM - mi1 * mj0) * itr;
            float t3 = (acc[mf][nf][3] * covInvM - mi1 * mj1) * itr;
            __half h0 = __float2half_rn(t0), h1 = __float2half_rn(t1);
            __half h2 = __float2half_rn(t2), h3 = __float2half_rn(t3);
            *(__half2*)(T + (long)r0 * C_ + c0)       = __halves2half2(h0, h1);
            *(__half2*)(T + (long)(r0 + 8) * C_ + c0) = __halves2half2(h2, h3);
            if (offdiag) {
                T[(long)c0 * C_ + r0]           = h0;
                T[(long)(c0 + 1) * C_ + r0]     = h1;
                T[(long)c0 * C_ + r0 + 8]       = h2;
                T[(long)(c0 + 1) * C_ + r0 + 8] = h3;
            }
        }
    }
}

// ================= fp16 power GEMM: D = P * Q^T (symmetric, upper-tri tiles) ============
// MODE 0: D = fp16(acc) ; MODE 1: D = fp16(2.25*T1 - 1.5*T2 + 0.25*acc)
#define PPAD 40
#define PT_H (128*PPAD)
#define PSTG (2*PT_H)
#define POW_SMEM (2*PSTG*2)

template<int MODE>
__global__ void __launch_bounds__(256)
pow_gemm(const __half* __restrict__ Pg, const __half* __restrict__ Qg,
         __half* __restrict__ Dg,
         const __half* __restrict__ T1g, const __half* __restrict__ T2g)
{
    extern __shared__ __half smh[];
    const int tid = threadIdx.x;
    const int b = blockIdx.z;
    const __half* P = Pg + (long)b * NSQ;
    const __half* Q = Qg + (long)b * NSQ;
    const int ib = c_bi[blockIdx.x] * 128;
    const int jb = c_bj[blockIdx.x] * 128;

    const int wid = tid >> 5, lane = tid & 31;
    const int wm = wid & 1, wn = wid >> 1;
    const int gid = lane >> 2, tig = lane & 3;

    float acc[4][4][4];
    #pragma unroll
    for (int mf = 0; mf < 4; mf++)
        #pragma unroll
        for (int nf = 0; nf < 4; nf++)
            #pragma unroll
            for (int e = 0; e < 4; e++) acc[mf][nf][e] = 0.f;

    uint4 ra[2], rb[2];
    #pragma unroll
    for (int q = 0; q < 2; q++) {
        int u = tid + q * 256; int r = u >> 2; int seg = u & 3;
        ra[q] = *(const uint4*)(P + (long)(ib + r) * C_ + seg * 8);
        rb[q] = *(const uint4*)(Q + (long)(jb + r) * C_ + seg * 8);
    }
    #pragma unroll
    for (int q = 0; q < 2; q++) {
        int u = tid + q * 256; int r = u >> 2; int seg = u & 3;
        *(uint4*)(smh + (long)r * PPAD + seg * 8)        = ra[q];
        *(uint4*)(smh + PT_H + (long)r * PPAD + seg * 8) = rb[q];
    }
    __syncthreads();

    for (int i = 0; i < 16; i++) {
        if (i + 1 < 16) {
            const int k0 = (i + 1) * 32;
            #pragma unroll
            for (int q = 0; q < 2; q++) {
                int u = tid + q * 256; int r = u >> 2; int seg = u & 3;
                ra[q] = *(const uint4*)(P + (long)(ib + r) * C_ + k0 + seg * 8);
                rb[q] = *(const uint4*)(Q + (long)(jb + r) * C_ + k0 + seg * 8);
            }
        }
        const __half* As = smh + (i & 1) * PSTG;
        const __half* Bs = As + PT_H;
        #pragma unroll
        for (int ks = 0; ks < 2; ks++) {
            uint32_t ah[4][4];
            #pragma unroll
            for (int mf = 0; mf < 4; mf++) {
                const __half* ap = As + (long)(wm * 64 + mf * 16 + gid) * PPAD + ks * 16 + tig * 2;
                ah[mf][0] = *(const uint32_t*)ap;
                ah[mf][1] = *(const uint32_t*)(ap + 8 * PPAD);
                ah[mf][2] = *(const uint32_t*)(ap + 8);
                ah[mf][3] = *(const uint32_t*)(ap + 8 * PPAD + 8);
            }
            uint32_t bf[4][2];
            #pragma unroll
            for (int nf = 0; nf < 4; nf++) {
                const __half* bp = Bs + (long)(wn * 32 + nf * 8 + gid) * PPAD + ks * 16 + tig * 2;
                bf[nf][0] = *(const uint32_t*)bp;
                bf[nf][1] = *(const uint32_t*)(bp + 8);
            }
            #pragma unroll
            for (int mf = 0; mf < 4; mf++)
                #pragma unroll
                for (int nf = 0; nf < 4; nf++)
                    mma_f16(acc[mf][nf], ah[mf], bf[nf]);
        }
        if (i + 1 < 16) {
            __half* Ad = smh + ((i + 1) & 1) * PSTG;
            #pragma unroll
            for (int q = 0; q < 2; q++) {
                int u = tid + q * 256; int r = u >> 2; int seg = u & 3;
                *(uint4*)(Ad + (long)r * PPAD + seg * 8)        = ra[q];
                *(uint4*)(Ad + PT_H + (long)r * PPAD + seg * 8) = rb[q];
            }
        }
        __syncthreads();
    }

    __half* D = Dg + (long)b * NSQ;
    const __half* T1 = T1g + (long)b * NSQ;
    const __half* T2 = T2g + (long)b * NSQ;
    const bool offdiag = (ib != jb);
    #pragma unroll
    for (int mf = 0; mf < 4; mf++) {
        const int r0 = ib + wm * 64 + mf * 16 + gid;
        #pragma unroll
        for (int nf = 0; nf < 4; nf++) {
            const int c0 = jb + wn * 32 + nf * 8 + tig * 2;
            float v0, v1, v2, v3;
            if (MODE == 0) {
                v0 = acc[mf][nf][0]; v1 = acc[mf][nf][1];
                v2 = acc[mf][nf][2]; v3 = acc[mf][nf][3];
            } else {
                float2 t1a = __half22float2(*(const __half2*)(T1 + (long)r0 * C_ + c0));
                float2 t2a = __half22float2(*(const __half2*)(T2 + (long)r0 * C_ + c0));
                float2 t1b = __half22float2(*(const __half2*)(T1 + (long)(r0 + 8) * C_ + c0));
                float2 t2b = __half22float2(*(const __half2*)(T2 + (long)(r0 + 8) * C_ + c0));
                v0 = 2.25f * t1a.x - 1.5f * t2a.x + 0.25f * acc[mf][nf][0];
                v1 = 2.25f * t1a.y - 1.5f * t2a.y + 0.25f * acc[mf][nf][1];
                v2 = 2.25f * t1b.x - 1.5f * t2b.x + 0.25f * acc[mf][nf][2];
                v3 = 2.25f * t1b.y - 1.5f * t2b.y + 0.25f * acc[mf][nf][3];
            }
            __half h0 = __float2half_rn(v0), h1 = __float2half_rn(v1);
            __half h2 = __float2half_rn(v2), h3 = __float2half_rn(v3);
            *(__half2*)(D + (long)r0 * C_ + c0)       = __halves2half2(h0, h1);
            *(__half2*)(D + (long)(r0 + 8) * C_ + c0) = __halves2half2(h2, h3);
            if (offdiag) {
                D[(long)c0 * C_ + r0]           = h0;
                D[(long)(c0 + 1) * C_ + r0]     = h1;
                D[(long)c0 * C_ + r0 + 8]       = h2;
                D[(long)(c0 + 1) * C_ + r0 + 8] = h3;
            }
        }
    }
}

// ================= Newton-Schulz vector chain: 16 matvecs =================
struct ChainCtx {
    const __half* S2;
    float* v;
    float* partial;
    float* pool;
    int    tid;
};

__device__ void mv(const __half* Ab, float* v, float* partial, int tid)
{
    const int cg = tid & 63;
    const int rg = tid >> 6;
    const __half* base = Ab + (long)rg * 64 * C_ + cg * 8;
    const float* vs = v + rg * 64;

    float a0 = 0.f, a1 = 0.f, a2 = 0.f, a3 = 0.f;
    float a4 = 0.f, a5 = 0.f, a6 = 0.f, a7 = 0.f;
    #pragma unroll 8
    for (int r = 0; r < 64; r++) {
        uint4 q = *(const uint4*)(base + (long)r * C_);
        float s = vs[r];
        float2 f0 = __half22float2(*(__half2*)&q.x);
        float2 f1 = __half22float2(*(__half2*)&q.y);
        float2 f2 = __half22float2(*(__half2*)&q.z);
        float2 f3 = __half22float2(*(__half2*)&q.w);
        a0 = fmaf(s, f0.x, a0);
        a1 = fmaf(s, f0.y, a1);
        a2 = fmaf(s, f1.x, a2);
        a3 = fmaf(s, f1.y, a3);
        a4 = fmaf(s, f2.x, a4);
        a5 = fmaf(s, f2.y, a5);
        a6 = fmaf(s, f3.x, a6);
        a7 = fmaf(s, f3.y, a7);
    }
    *(float4*)(partial + rg * 512 + cg * 8)     = make_float4(a0, a1, a2, a3);
    *(float4*)(partial + rg * 512 + cg * 8 + 4) = make_float4(a4, a5, a6, a7);
    __syncthreads();
    float sum = 0.f;
    #pragma unroll
    for (int g = 0; g < 8; g++) sum += partial[g * 512 + tid];
    v[tid] = sum;
    __syncthreads();
}

__device__ void applyW_direct(const __half* Ab, float* v, float* partial,
                              float* save, int tid)
{
    save[tid] = v[tid];
    __syncthreads();
    mv(Ab, v, partial, tid);
    float nv = 1.5f * save[tid] - 0.5f * v[tid];
    __syncthreads();
    v[tid] = nv;
    __syncthreads();
}

__device__ void exec_W(int k0, ChainCtx& c)
{
    int ty[16], kk[16], sp[16], st[16];
    int top = 0;
    ty[0] = 0; kk[0] = k0; sp[0] = 0; st[0] = 0; top = 1;
    while (top > 0) {
        const int i = top - 1;
        if (ty[i] == 0) {
            if (st[i] == 0) {
                float* save = c.pool + sp[i] * 512;
                save[c.tid] = c.v[c.tid];
                __syncthreads();
                st[i] = 1;
                ty[top] = 1; kk[top] = kk[i]; sp[top] = sp[i] + 1; st[top] = 0; top++;
            } else {
                float* save = c.pool + sp[i] * 512;
                float nv = 1.5f * save[c.tid] - 0.5f * c.v[c.tid];
                __syncthreads();
                c.v[c.tid] = nv;
                __syncthreads();
                top--;
            }
        } else {
            if (kk[i] == 2) { mv(c.S2, c.v, c.partial, c.tid); top--; }
            else if (st[i] == 0) {
                st[i] = 1;
                ty[top] = 1; kk[top] = kk[i] - 1; sp[top] = sp[i]; st[top] = 0; top++;
            } else if (st[i] == 1) {
                st[i] = 2;
                ty[top] = 0; kk[top] = kk[i] - 1; sp[top] = sp[i]; st[top] = 0; top++;
            } else if (st[i] == 2) {
                st[i] = 3;
                ty[top] = 0; kk[top] = kk[i] - 1; sp[top] = sp[i]; st[top] = 0; top++;
            } else top--;
        }
    }
}

__global__ void __launch_bounds__(512, 1)
chain_kernel(const __half* __restrict__ Th, const __half* __restrict__ S1h,
             const __half* __restrict__ S2h,
             const float* __restrict__ str, float* __restrict__ cs)
{
    __shared__ float v[512];
    __shared__ float partial[8 * 512];
    __shared__ float pool[5 * 512];
    const int b = blockIdx.x;
    const int tid = threadIdx.x;

    const __half* T  = Th  + (long)b * NSQ;
    const __half* S1 = S1h + (long)b * NSQ;

    ChainCtx c;
    c.S2 = S2h + (long)b * NSQ;
    c.v = v; c.partial = partial; c.pool = pool;
    c.tid = tid;

    v[tid] = 1.0f;
    __syncthreads();

    mv(T, v, partial, tid);
    applyW_direct(T,  v, partial, pool, tid);
    applyW_direct(S1, v, partial, pool, tid);
    for (int k = 2; k <= 4; k++)
        exec_W(k, c);

    cs[b * C_ + tid] = v[tid] * str[b] * (1.0f / C_);
}

// ---------------- out = cov_sum * x ----------------
__global__ void scale_kernel(const float* __restrict__ x,
                             const float* __restrict__ cs, float* __restrict__ out)
{
    long i4 = (long)blockIdx.x * blockDim.x + threadIdx.x;
    const long total4 = (long)B_ * C_ * M_ / 4;
    if (i4 >= total4) return;
    long e = i4 * 4;
    int bc = (int)(e / M_);
    float s = cs[bc];
    float4 v = *(const float4*)(x + e);
    v.x *= s; v.y *= s; v.z *= s; v.w *= s;
    *(float4*)(out + e) = v;
}

// ---------------- launcher ----------------
extern "C" void kernel_launch(void* const* d_in, const int* in_sizes, int n_in,
                              void* d_out, int out_size)
{
    const float* x = (const float*)d_in[0];
    float* out = (float*)d_out;

    float *mean, *ssq, *itr, *str, *cs;
    __half *xh, *xl, *Th, *P2, *S1h, *S2h;
    cudaGetSymbolAddress((void**)&xh,   g_xh);
    cudaGetSymbolAddress((void**)&xl,   g_xl);
    cudaGetSymbolAddress((void**)&Th,   g_Th);
    cudaGetSymbolAddress((void**)&P2,   g_P2);
    cudaGetSymbolAddress((void**)&S1h,  g_S1h);
    cudaGetSymbolAddress((void**)&S2h,  g_S2h);
    cudaGetSymbolAddress((void**)&mean, g_mean);
    cudaGetSymbolAddress((void**)&ssq,  g_ssq);
    cudaGetSymbolAddress((void**)&itr,  g_itr);
    cudaGetSymbolAddress((void**)&str,  g_str);
    cudaGetSymbolAddress((void**)&cs,   g_cs);

    cudaFuncSetAttribute(cov_gemm_h, cudaFuncAttributeMaxDynamicSharedMemorySize, COV_SMEM);
    cudaFuncSetAttribute(pow_gemm<0>, cudaFuncAttributeMaxDynamicSharedMemorySize, POW_SMEM);
    cudaFuncSetAttribute(pow_gemm<1>, cudaFuncAttributeMaxDynamicSharedMemorySize, POW_SMEM);

    // 1) split x into fp16 hi/lo ; row means + sum-of-squares
    const long ng = (long)B_ * C_ * (MPAD / 8);
    splitx_kernel<<<(int)((ng + 255) / 256), 256>>>(x, xh, xl);
    mean_kernel<<<(B_*C_ + 7) / 8, 256>>>(x, mean, ssq);

    // 2) trace from mean/ssq (before the GEMM)
    tracex_kernel<<<B_, 512>>>(mean, ssq, itr, str);

    // 3) T directly in fp16 via split-fp16 HMMA (upper-tri + mirror)
    cov_gemm_h<<<dim3(10, 1, B_), 256, COV_SMEM>>>(xh, xl, Th, mean, itr);

    // 4) S1 = cubic(T) ; S2 = cubic(S1)   (symmetric tiles)
    const dim3 pg(10, 1, B_);
    pow_gemm<0><<<pg, 256, POW_SMEM>>>(Th,  Th,  P2,  Th,  Th);
    pow_gemm<1><<<pg, 256, POW_SMEM>>>(P2,  Th,  S1h, Th,  P2);
    pow_gemm<0><<<pg, 256, POW_SMEM>>>(S1h, S1h, P2,  S1h, S1h);
    pow_gemm<1><<<pg, 256, POW_SMEM>>>(P2,  S1h, S2h, S1h, P2);

    // 5) chain: 16 matvecs (2 T, 1 S1, 13 S2)
    chain_kernel<<<B_, 512>>>(Th, S1h, S2h, str, cs);

    // 6) out = cov_sum[b][c] * x
    const long total4 = (long)B_ * C_ * M_ / 4;
    scale_kernel<<<(int)((total4 + 255) / 256), 256>>>(x, cs, out);

    (void)in_sizes; (void)n_in; (void)out_size;
}